// round 10
// baseline (speedup 1.0000x reference)
#include <cuda_runtime.h>
#include <cuda_bf16.h>
#include <math.h>
#include <stdint.h>

#define B_   32
#define NN   1024
#define FIN  512
#define H1_  256
#define H2_  128
#define TOT  32768

// ---------------- scratch (device globals; no allocation allowed) ----------
__device__ float d_g1[B_ * NN * H1_];
__device__ float d_elP[2 * TOT];
__device__ float d_erP[2 * TOT];
__device__ float d_stat[B_ * 2];
__device__ float d_gv[B_ * NN];
// transposed + bf16-split B operands ([N][K] layout)
__device__ __nv_bfloat16 d_ht1_hi[B_ * H1_ * NN];
__device__ __nv_bfloat16 d_ht1_lo[B_ * H1_ * NN];
__device__ __nv_bfloat16 d_ht2_hi[B_ * H2_ * NN];
__device__ __nv_bfloat16 d_ht2_lo[B_ * H2_ * NN];
__device__ __nv_bfloat16 d_wt1_hi[H1_ * FIN];
__device__ __nv_bfloat16 d_wt1_lo[H1_ * FIN];
__device__ __nv_bfloat16 d_wt2_hi[H2_ * H1_];
__device__ __nv_bfloat16 d_wt2_lo[H2_ * H1_];

__device__ __forceinline__ uint32_t smem_u32(const void* p) {
    return (uint32_t)__cvta_generic_to_shared(p);
}
__device__ __forceinline__ uint32_t sw64(uint32_t off) {
    return off ^ ((off >> 3) & 0x30);
}
__device__ __forceinline__ float attf(float x, float mn, float kk) {
    float lr = x >= 0.f ? x : 0.01f * x;
    return 1.f / (1.f + __expf(-(fmaf(lr - mn, kk, -20.f))));
}
__device__ __forceinline__ void ldx4(unsigned* r, uint32_t addr) {
    asm volatile("ldmatrix.sync.aligned.m8n8.x4.shared.b16 {%0,%1,%2,%3}, [%4];"
                 : "=r"(r[0]), "=r"(r[1]), "=r"(r[2]), "=r"(r[3]) : "r"(addr));
}
__device__ __forceinline__ void ldx2(unsigned* r, uint32_t addr) {
    asm volatile("ldmatrix.sync.aligned.m8n8.x2.shared.b16 {%0,%1}, [%2];"
                 : "=r"(r[0]), "=r"(r[1]) : "r"(addr));
}
__device__ __forceinline__ void mma16816(float* c, const unsigned* a, const unsigned* b) {
    asm volatile(
        "mma.sync.aligned.m16n8k16.row.col.f32.bf16.bf16.f32 "
        "{%0,%1,%2,%3}, {%4,%5,%6,%7}, {%8,%9}, {%0,%1,%2,%3};"
        : "+f"(c[0]), "+f"(c[1]), "+f"(c[2]), "+f"(c[3])
        : "r"(a[0]), "r"(a[1]), "r"(a[2]), "r"(a[3]), "r"(b[0]), "r"(b[1]));
}
__device__ __forceinline__ void cpasync16(uint32_t saddr, const void* gptr) {
    asm volatile("cp.async.cg.shared.global [%0], [%1], 16;"
                 :: "r"(saddr), "l"(gptr) : "memory");
}
#define CP_COMMIT() asm volatile("cp.async.commit_group;" ::: "memory")
#define CP_WAIT0()  asm volatile("cp.async.wait_group 0;" ::: "memory")

__device__ __forceinline__ uint32_t packsplit(float x0, float x1, uint32_t& lo) {
    __nv_bfloat16 h0 = __float2bfloat16(x0), h1 = __float2bfloat16(x1);
    float r0 = x0 - __bfloat162float(h0);
    float r1 = x1 - __bfloat162float(h1);
    __nv_bfloat16 l0 = __float2bfloat16(r0), l1 = __float2bfloat16(r1);
    lo = (uint32_t)__bfloat16_as_ushort(l0) | ((uint32_t)__bfloat16_as_ushort(l1) << 16);
    return (uint32_t)__bfloat16_as_ushort(h0) | ((uint32_t)__bfloat16_as_ushort(h1) << 16);
}

// ---------------- tensor-core GEMM: C[M,N] = A[M,K] @ Bt^T -------------------
// A: [M,K] fp32 (MODE 0) or att(elP,erP,stat) on the fly (MODE 1; MODE 2 also
// writes fp32 att to attOut — requires gridDim.x == 1). Bt: bf16 hi/lo [N][K].
// CTA tile 128x128, BK=32, 8 warps (2m x 4n), warp tile 64x32, m16n8k16.
// bf16x3: hi*hi + lo*hi + hi*lo. EPI: 0 none, 1 ELU. 2 CTAs/SM, SW64 smem.
// TR: 0 = write fp32 C. 1/2 = DO NOT write C; instead write transposed bf16
// hi/lo planes (htHi/htLo, [b][feat][node]) + el/er dual-dot partials:
// TR 1 -> part = n0>>7 (two n-CTAs); TR 2 -> part0 = value, part1 = 0.
template <int MODE, int EPI, int TR>
__global__ void __launch_bounds__(256, 2)
tc_gemm(const float* __restrict__ A,
        const __nv_bfloat16* __restrict__ Bhi, const __nv_bfloat16* __restrict__ Blo,
        float* __restrict__ C, int N, int K,
        long long sA, long long sBt, long long sC,
        const float* __restrict__ elP, const float* __restrict__ erP,
        const float* __restrict__ stat, float* __restrict__ attOut,
        const float* __restrict__ av, int NF,
        __nv_bfloat16* __restrict__ htHi, __nv_bfloat16* __restrict__ htLo,
        float* __restrict__ elO, float* __restrict__ erO)
{
    extern __shared__ char smem[];
    // per buffer: A_hi 8K | A_lo 8K | B_hi 8K | B_lo 8K = 32K; two buffers
    constexpr int BUF = 32768;
    constexpr int OAH = 0, OAL = 8192, OBH = 16384, OBL = 24576;

    const int bz = blockIdx.z;
    if (MODE == 0) A += (long long)bz * sA;
    Bhi += (long long)bz * sBt;
    Blo += (long long)bz * sBt;
    if (TR == 0) C += (long long)bz * sC;

    const int m0 = blockIdx.y * 128;
    const int n0 = blockIdx.x * 128;
    const int tid  = threadIdx.x;
    const int warp = tid >> 5, lane = tid & 31;
    const int mw = (warp >> 2) * 64;     // warp row base in tile
    const int nw = (warp & 3) * 32;      // warp col base in tile

    const uint32_t sb = smem_u32(smem);

    // A producer mapping: row = tid>>1 (0..127), 16-col half (tid&1)
    const int ar = tid >> 1;
    const int ac = (tid & 1) * 16;
    float elv = 0.f, mn = 0.f, kk = 0.f;
    if (MODE != 0) {
        elv = elP[bz * NN + m0 + ar] + elP[TOT + bz * NN + m0 + ar];
        mn  = stat[bz * 2 + 0];
        kk  = stat[bz * 2 + 1];
    }

    float va[16];

    // ---- load A-source for chunk c into registers (pure LDG) ----
    auto produce_load = [&](int c) {
        const int k0 = c << 5;
        if (MODE == 0) {
            const float4* Sp = (const float4*)(A + (long long)(m0 + ar) * K + k0 + ac);
#pragma unroll
            for (int q = 0; q < 4; q++) {
                float4 f = Sp[q];
                va[q * 4 + 0] = f.x; va[q * 4 + 1] = f.y;
                va[q * 4 + 2] = f.z; va[q * 4 + 3] = f.w;
            }
        } else {
            const float4* E0 = (const float4*)(erP + bz * NN + k0 + ac);
            const float4* E1 = (const float4*)(erP + TOT + bz * NN + k0 + ac);
#pragma unroll
            for (int q = 0; q < 4; q++) {
                float4 f = E0[q];
                float4 g = E1[q];
                va[q * 4 + 0] = f.x + g.x; va[q * 4 + 1] = f.y + g.y;
                va[q * 4 + 2] = f.z + g.z; va[q * 4 + 3] = f.w + g.w;
            }
        }
    };

    // ---- B planes straight to smem via cp.async ----
    auto produce_B = [&](int c, int buf) {
        const int k0 = c << 5;
        const uint32_t dH = sb + buf * BUF + OBH;
        const uint32_t dL = sb + buf * BUF + OBL;
#pragma unroll
        for (int rep = 0; rep < 2; rep++) {
            int idx = tid + rep * 256;         // 0..511 granules per plane
            int row = idx >> 2, q = idx & 3;
            uint32_t so = sw64(row * 64 + q * 16);
            cpasync16(dH + so, Bhi + (long long)(n0 + row) * K + k0 + q * 8);
            cpasync16(dL + so, Blo + (long long)(n0 + row) * K + k0 + q * 8);
        }
        CP_COMMIT();
    };

    // ---- finish A: attf (MODE!=0), split to hi/lo, STS (+ STG att, MODE 2) --
    auto produce_store = [&](int c, int buf) {
        char* base = smem + buf * BUF;
        if (MODE != 0) {
#pragma unroll
            for (int e = 0; e < 16; e++) va[e] = attf(elv + va[e], mn, kk);
            if (MODE == 2) {
                const int k0 = c << 5;
                float4* Op = (float4*)(attOut + (long long)bz * NN * NN +
                                       (long long)(m0 + ar) * NN + k0 + ac);
#pragma unroll
                for (int q = 0; q < 4; q++)
                    Op[q] = make_float4(va[q * 4], va[q * 4 + 1], va[q * 4 + 2], va[q * 4 + 3]);
            }
        }
#pragma unroll
        for (int g = 0; g < 2; g++) {
            uint4 hq, lq;
            uint32_t* hw = (uint32_t*)&hq;
            uint32_t* lw = (uint32_t*)&lq;
#pragma unroll
            for (int e = 0; e < 4; e++)
                hw[e] = packsplit(va[g * 8 + e * 2], va[g * 8 + e * 2 + 1], lw[e]);
            uint32_t so = sw64(ar * 64 + ac * 2 + g * 16);
            *(uint4*)(base + OAH + so) = hq;
            *(uint4*)(base + OAL + so) = lq;
        }
    };

    float acc[4][4][4] = {};

    auto consume = [&](int buf) {
        const uint32_t aH = sb + buf * BUF + OAH;
        const uint32_t aL = sb + buf * BUF + OAL;
        const uint32_t bH = sb + buf * BUF + OBH;
        const uint32_t bL = sb + buf * BUF + OBL;
        const uint32_t aRow = (lane & 15);
        const uint32_t aKof = (lane >> 4) * 16;
        const uint32_t bRow = (lane & 7);
        const uint32_t bKof = ((lane >> 3) & 1) * 16;
#pragma unroll
        for (int ks = 0; ks < 2; ks++) {
            const uint32_t kb = ks * 32;       // byte col of k0+ks*16
            unsigned ah[4][4], al[4][4], bh[4][2], bl[4][2];
#pragma unroll
            for (int mt = 0; mt < 4; mt++) {
                uint32_t off = sw64((mw + mt * 16 + aRow) * 64 + kb + aKof);
                ldx4(ah[mt], aH + off);
                ldx4(al[mt], aL + off);
            }
#pragma unroll
            for (int nt = 0; nt < 4; nt++) {
                uint32_t off = sw64((nw + nt * 8 + bRow) * 64 + kb + bKof);
                ldx2(bh[nt], bH + off);
                ldx2(bl[nt], bL + off);
            }
#pragma unroll
            for (int mt = 0; mt < 4; mt++) {
#pragma unroll
                for (int nt = 0; nt < 4; nt++) {
                    mma16816(acc[mt][nt], ah[mt], bh[nt]);
                    mma16816(acc[mt][nt], al[mt], bh[nt]);
                    mma16816(acc[mt][nt], ah[mt], bl[nt]);
                }
            }
        }
    };

    const int nCh = K >> 5;
    // prologue
    produce_load(0);
    produce_B(0, 0);
    produce_store(0, 0);
    CP_WAIT0();
    __syncthreads();

    int buf = 0;
    for (int c = 0; c < nCh; c++) {
        const bool more = (c + 1 < nCh);
        if (more) {
            produce_load(c + 1);       // LDG issued; latency covered by consume
            produce_B(c + 1, buf ^ 1); // cp.async, off-thread
        }
        consume(buf);
        if (more) produce_store(c + 1, buf ^ 1);
        CP_WAIT0();
        __syncthreads();
        buf ^= 1;
    }

    // ---- epilogue ----
    const int r0 = lane >> 2;
    const int cc = (lane & 3) * 2;
    if (TR == 0) {
#pragma unroll
        for (int mt = 0; mt < 4; mt++) {
#pragma unroll
            for (int nt = 0; nt < 4; nt++) {
                float* a4 = acc[mt][nt];
                if (EPI == 1) {
#pragma unroll
                    for (int e = 0; e < 4; e++)
                        a4[e] = a4[e] > 0.f ? a4[e] : (__expf(a4[e]) - 1.f);
                }
                const int col = n0 + nw + nt * 8 + cc;
                const int row = m0 + mw + mt * 16 + r0;
                *(float2*)&C[(long long)row * N + col]       = make_float2(a4[0], a4[1]);
                *(float2*)&C[(long long)(row + 8) * N + col] = make_float2(a4[2], a4[3]);
            }
        }
    } else {
        // stage tile to smem fp32 [128][129]
        __syncthreads();
        float* ts = (float*)smem;
#pragma unroll
        for (int mt = 0; mt < 4; mt++) {
#pragma unroll
            for (int nt = 0; nt < 4; nt++) {
                float* a4 = acc[mt][nt];
                const int row = mw + mt * 16 + r0;
                const int col = nw + nt * 8 + cc;
                ts[row * 129 + col]           = a4[0];
                ts[row * 129 + col + 1]       = a4[1];
                ts[(row + 8) * 129 + col]     = a4[2];
                ts[(row + 8) * 129 + col + 1] = a4[3];
            }
        }
        __syncthreads();
        // el/er partial dual-dot: thread = (row, feat-half)
        {
            const int row = tid >> 1;
            const int hf  = tid & 1;
            const float* tr = ts + row * 129 + hf * 64;
            const float* aLp = av + n0 + hf * 64;
            const float* aRp = av + NF + n0 + hf * 64;
            float sl = 0.f, sr = 0.f;
#pragma unroll
            for (int f = 0; f < 64; f++) {
                float v = tr[f];
                sl = fmaf(v, aLp[f], sl);
                sr = fmaf(v, aRp[f], sr);
            }
            sl += __shfl_xor_sync(0xFFFFFFFFu, sl, 1);
            sr += __shfl_xor_sync(0xFFFFFFFFu, sr, 1);
            if (hf == 0) {
                const int grow = m0 + row;
                if (TR == 1) {
                    const int part = n0 >> 7;
                    elO[part * TOT + grow] = sl;
                    erO[part * TOT + grow] = sr;
                } else {
                    elO[grow] = sl; elO[TOT + grow] = 0.f;
                    erO[grow] = sr; erO[TOT + grow] = 0.f;
                }
            }
        }
        // transposed bf16 hi/lo write: thread = (feat, node-half)
        {
            const int f  = tid >> 1;
            const int hf = tid & 1;
            const int b  = m0 >> 10;
            const int node0 = (m0 & 1023) + hf * 64;
            __nv_bfloat16* dh = htHi + ((long long)(b * NF + n0 + f) * NN) + node0;
            __nv_bfloat16* dl = htLo + ((long long)(b * NF + n0 + f) * NN) + node0;
#pragma unroll
            for (int i0 = 0; i0 < 64; i0 += 8) {
                uint4 hq, lq;
                uint32_t* hw = (uint32_t*)&hq;
                uint32_t* lw = (uint32_t*)&lq;
#pragma unroll
                for (int e = 0; e < 4; e++) {
                    float x0 = ts[(hf * 64 + i0 + e * 2)     * 129 + f];
                    float x1 = ts[(hf * 64 + i0 + e * 2 + 1) * 129 + f];
                    hw[e] = packsplit(x0, x1, lw[e]);
                }
                *(uint4*)(dh + i0) = hq;
                *(uint4*)(dl + i0) = lq;
            }
        }
    }
}

// ---------------- transpose + bf16 split (weights only) ---------------------
__global__ void prepT(const float* __restrict__ src, __nv_bfloat16* __restrict__ dhi,
                      __nv_bfloat16* __restrict__ dlo, int R, int Cc)
{
    __shared__ float t[32][33];
    const int c0 = blockIdx.x * 32;
    const int r0 = blockIdx.y * 32;
    const int tx = threadIdx.x, ty = threadIdx.y;
#pragma unroll
    for (int i = ty; i < 32; i += 8)
        t[i][tx] = src[(long long)(r0 + i) * Cc + c0 + tx];
    __syncthreads();
#pragma unroll
    for (int i = ty; i < 32; i += 8) {
        float v = t[tx][i];
        __nv_bfloat16 h = __float2bfloat16(v);
        float rr = v - __bfloat162float(h);
        dhi[(long long)(c0 + i) * R + r0 + tx] = h;
        dlo[(long long)(c0 + i) * R + r0 + tx] = __float2bfloat16(rr);
    }
}

// ---------------- per-batch min/max of separable e --------------------------
__global__ void minmax_stats(const float* __restrict__ elP, const float* __restrict__ erP,
                             float* __restrict__ stat)
{
    const int b = blockIdx.x;
    const int tid = threadIdx.x;
    float mnl = 1e30f, mxl = -1e30f, mnr = 1e30f, mxr = -1e30f;
    for (int i = tid; i < NN; i += 256) {
        float l = elP[b * NN + i] + elP[TOT + b * NN + i];
        float r = erP[b * NN + i] + erP[TOT + b * NN + i];
        mnl = fminf(mnl, l); mxl = fmaxf(mxl, l);
        mnr = fminf(mnr, r); mxr = fmaxf(mxr, r);
    }
#pragma unroll
    for (int o = 16; o; o >>= 1) {
        mnl = fminf(mnl, __shfl_xor_sync(0xFFFFFFFFu, mnl, o));
        mxl = fmaxf(mxl, __shfl_xor_sync(0xFFFFFFFFu, mxl, o));
        mnr = fminf(mnr, __shfl_xor_sync(0xFFFFFFFFu, mnr, o));
        mxr = fmaxf(mxr, __shfl_xor_sync(0xFFFFFFFFu, mxr, o));
    }
    __shared__ float s[4][8];
    const int w = tid >> 5, lane = tid & 31;
    if (lane == 0) { s[0][w] = mnl; s[1][w] = mxl; s[2][w] = mnr; s[3][w] = mxr; }
    __syncthreads();
    if (tid == 0) {
        float a0 = s[0][0], a1 = s[1][0], a2 = s[2][0], a3 = s[3][0];
#pragma unroll
        for (int i = 1; i < 8; i++) {
            a0 = fminf(a0, s[0][i]); a1 = fmaxf(a1, s[1][i]);
            a2 = fminf(a2, s[2][i]); a3 = fmaxf(a3, s[3][i]);
        }
        float lo = a0 + a2, hi = a1 + a3;
        float mn = lo >= 0.f ? lo : 0.01f * lo;
        float mx = hi >= 0.f ? hi : 0.01f * hi;
        stat[b * 2 + 0] = mn;
        stat[b * 2 + 1] = 30.f / (mx - mn);
    }
}

// ---------------- gv = g2 @ Wg ----------------------------------------------
__global__ void gv_kernel(const float* __restrict__ g2, const float* __restrict__ Wg,
                          float* __restrict__ gv)
{
    const int row  = (blockIdx.x * blockDim.x + threadIdx.x) >> 5;
    const int lane = threadIdx.x & 31;
    const float* gp = g2 + (long long)row * H2_;
    float s = fmaf(gp[lane], Wg[lane], gp[lane + 32] * Wg[lane + 32]);
    s = fmaf(gp[lane + 64], Wg[lane + 64], s);
    s = fmaf(gp[lane + 96], Wg[lane + 96], s);
#pragma unroll
    for (int o = 16; o; o >>= 1) s += __shfl_xor_sync(0xFFFFFFFFu, s, o);
    if (lane == 0) gv[row] = s;
}

// ---------------- out = leaky(fc2 @ gv + bg) ----------------------------------
__global__ void z_kernel(const float* __restrict__ fc2, const float* __restrict__ gv,
                         const float* __restrict__ bg, float* __restrict__ out)
{
    const int row  = (blockIdx.x * blockDim.x + threadIdx.x) >> 5;
    const int lane = threadIdx.x & 31;
    const int b = row >> 10;
    const float* fr = fc2 + (long long)row * NN;
    const float* gr = gv + b * NN;
    float s = 0.f;
#pragma unroll
    for (int j = lane * 4; j < NN; j += 128) {
        float4 f = *(const float4*)&fr[j];
        float4 g = *(const float4*)&gr[j];
        s = fmaf(f.x, g.x, s); s = fmaf(f.y, g.y, s);
        s = fmaf(f.z, g.z, s); s = fmaf(f.w, g.w, s);
    }
#pragma unroll
    for (int o = 16; o; o >>= 1) s += __shfl_xor_sync(0xFFFFFFFFu, s, o);
    if (lane == 0) {
        float z = s + bg[0];
        out[row] = z >= 0.f ? z : 0.01f * z;
    }
}

// ---------------------------------------------------------------------------
template <typename T>
static T* sym_p(const void* s)
{
    void* p = nullptr;
    cudaGetSymbolAddress(&p, s);
    return (T*)p;
}

extern "C" void kernel_launch(void* const* d_in, const int* in_sizes, int n_in,
                              void* d_out, int out_size)
{
    const float* x  = (const float*)d_in[0];
    const float* W1 = (const float*)d_in[2];
    const float* a1 = (const float*)d_in[3];
    const float* W2 = (const float*)d_in[4];
    const float* a2 = (const float*)d_in[5];
    const float* Wg = (const float*)d_in[6];
    const float* bg = (const float*)d_in[7];

    float* out = (float*)d_out;
    float* fc2 = out + (long long)B_ * NN;
    float* g2  = fc2 + (long long)B_ * NN * NN;

    float* g1   = sym_p<float>(d_g1);
    float* elP  = sym_p<float>(d_elP);
    float* erP  = sym_p<float>(d_erP);
    float* stat = sym_p<float>(d_stat);
    float* gv   = sym_p<float>(d_gv);
    __nv_bfloat16* ht1h = sym_p<__nv_bfloat16>(d_ht1_hi);
    __nv_bfloat16* ht1l = sym_p<__nv_bfloat16>(d_ht1_lo);
    __nv_bfloat16* ht2h = sym_p<__nv_bfloat16>(d_ht2_hi);
    __nv_bfloat16* ht2l = sym_p<__nv_bfloat16>(d_ht2_lo);
    __nv_bfloat16* wt1h = sym_p<__nv_bfloat16>(d_wt1_hi);
    __nv_bfloat16* wt1l = sym_p<__nv_bfloat16>(d_wt1_lo);
    __nv_bfloat16* wt2h = sym_p<__nv_bfloat16>(d_wt2_hi);
    __nv_bfloat16* wt2l = sym_p<__nv_bfloat16>(d_wt2_lo);

    const int SMB    = 2 * 32768;           // 64 KB (TR=0)
    const int SMB_TR = 128 * 129 * 4 + 512; // 66.5 KB (TR>0: staging needs more)
    cudaFuncSetAttribute(tc_gemm<0, 0, 1>, cudaFuncAttributeMaxDynamicSharedMemorySize, SMB_TR);
    cudaFuncSetAttribute(tc_gemm<1, 1, 0>, cudaFuncAttributeMaxDynamicSharedMemorySize, SMB);
    cudaFuncSetAttribute(tc_gemm<0, 0, 2>, cudaFuncAttributeMaxDynamicSharedMemorySize, SMB_TR);
    cudaFuncSetAttribute(tc_gemm<2, 0, 0>, cudaFuncAttributeMaxDynamicSharedMemorySize, SMB);

    const int rowsTot = B_ * NN;              // 32768
    const dim3 tp(32, 8);

    // ===== weight preps (tiny) =====
    prepT<<<dim3(H1_ / 32, FIN / 32, 1), tp>>>(W1, wt1h, wt1l, FIN, H1_);
    prepT<<<dim3(H2_ / 32, H1_ / 32, 1), tp>>>(W2, wt2h, wt2l, H1_, H2_);

    // ===== Layer 1 =====
    // h1 = x @ W1, fused: writes ht1 hi/lo (transposed split) + el/er parts
    tc_gemm<0, 0, 1><<<dim3(H1_ / 128, rowsTot / 128, 1), 256, SMB_TR>>>(
        x, wt1h, wt1l, nullptr, H1_, FIN, 0, 0, 0,
        nullptr, nullptr, nullptr, nullptr, a1, H1_, ht1h, ht1l, elP, erP);
    minmax_stats<<<B_, 256>>>(elP, erP, stat);
    // g1 = elu(att1 @ h1), att1 on the fly
    tc_gemm<1, 1, 0><<<dim3(H1_ / 128, NN / 128, B_), 256, SMB>>>(
        nullptr, ht1h, ht1l, g1, H1_, NN,
        0, (long long)H1_ * NN, (long long)NN * H1_,
        elP, erP, stat, nullptr, nullptr, 0, nullptr, nullptr, nullptr, nullptr);

    // ===== Layer 2 =====
    // h2 = g1 @ W2, fused: writes ht2 hi/lo + el/er (part1 zeroed)
    tc_gemm<0, 0, 2><<<dim3(H2_ / 128, rowsTot / 128, 1), 256, SMB_TR>>>(
        g1, wt2h, wt2l, nullptr, H2_, H1_, 0, 0, 0,
        nullptr, nullptr, nullptr, nullptr, a2, H2_, ht2h, ht2l, elP, erP);
    minmax_stats<<<B_, 256>>>(elP, erP, stat);
    // g2 = fc2 @ h2; fc2 written on the fly (gridDim.x == 1)
    tc_gemm<2, 0, 0><<<dim3(H2_ / 128, NN / 128, B_), 256, SMB>>>(
        nullptr, ht2h, ht2l, g2, H2_, NN,
        0, (long long)H2_ * NN, (long long)NN * H2_,
        elP, erP, stat, fc2, nullptr, 0, nullptr, nullptr, nullptr, nullptr);

    // ===== Head: out = leaky(fc2 @ (g2 @ Wg) + bg) =====
    gv_kernel<<<rowsTot / 8, 256>>>(g2, Wg, gv);
    z_kernel<<<rowsTot / 8, 256>>>(fc2, gv, bg, out);
}

// round 12
// speedup vs baseline: 1.0946x; 1.0946x over previous
#include <cuda_runtime.h>
#include <cuda_fp16.h>
#include <math.h>
#include <stdint.h>

#define B_   32
#define NN   1024
#define FIN  512
#define H1_  256
#define H2_  128
#define TOT  32768

// ---------------- scratch (device globals; no allocation allowed) ----------
__device__ float d_g1[B_ * NN * H1_];
__device__ float d_elP[2 * TOT];
__device__ float d_erP[2 * TOT];
__device__ float d_stat[B_ * 2];
__device__ float d_gv[B_ * NN];
// transposed fp16 B operands ([N][K] layout)
__device__ __half d_ht1[B_ * H1_ * NN];     // quantized single plane
__device__ __half d_ht2[B_ * H2_ * NN];     // quantized single plane
__device__ __half d_wt1_hi[H1_ * FIN];      // exact hi/lo split
__device__ __half d_wt1_lo[H1_ * FIN];
__device__ __half d_wt2_hi[H2_ * H1_];
__device__ __half d_wt2_lo[H2_ * H1_];

__device__ __forceinline__ uint32_t smem_u32(const void* p) {
    return (uint32_t)__cvta_generic_to_shared(p);
}
__device__ __forceinline__ uint32_t sw64(uint32_t off) {
    return off ^ ((off >> 3) & 0x30);
}
__device__ __forceinline__ float attf(float x, float mn, float kk) {
    float lr = x >= 0.f ? x : 0.01f * x;
    return 1.f / (1.f + __expf(-(fmaf(lr - mn, kk, -20.f))));
}
__device__ __forceinline__ void ldx4(unsigned* r, uint32_t addr) {
    asm volatile("ldmatrix.sync.aligned.m8n8.x4.shared.b16 {%0,%1,%2,%3}, [%4];"
                 : "=r"(r[0]), "=r"(r[1]), "=r"(r[2]), "=r"(r[3]) : "r"(addr));
}
__device__ __forceinline__ void ldx2(unsigned* r, uint32_t addr) {
    asm volatile("ldmatrix.sync.aligned.m8n8.x2.shared.b16 {%0,%1}, [%2];"
                 : "=r"(r[0]), "=r"(r[1]) : "r"(addr));
}
__device__ __forceinline__ void mma16816(float* c, const unsigned* a, const unsigned* b) {
    asm volatile(
        "mma.sync.aligned.m16n8k16.row.col.f32.f16.f16.f32 "
        "{%0,%1,%2,%3}, {%4,%5,%6,%7}, {%8,%9}, {%0,%1,%2,%3};"
        : "+f"(c[0]), "+f"(c[1]), "+f"(c[2]), "+f"(c[3])
        : "r"(a[0]), "r"(a[1]), "r"(a[2]), "r"(a[3]), "r"(b[0]), "r"(b[1]));
}
__device__ __forceinline__ void cpasync16(uint32_t saddr, const void* gptr) {
    asm volatile("cp.async.cg.shared.global [%0], [%1], 16;"
                 :: "r"(saddr), "l"(gptr) : "memory");
}
#define CP_COMMIT() asm volatile("cp.async.commit_group;" ::: "memory")
#define CP_WAIT0()  asm volatile("cp.async.wait_group 0;" ::: "memory")

// exact split: x = hi + lo (both fp16); returns packed hi pair, writes lo pair
__device__ __forceinline__ uint32_t packsplit(float x0, float x1, uint32_t& lo) {
    __half h0 = __float2half_rn(x0), h1 = __float2half_rn(x1);
    float r0 = x0 - __half2float(h0);
    float r1 = x1 - __half2float(h1);
    __half l0 = __float2half_rn(r0), l1 = __float2half_rn(r1);
    lo = (uint32_t)__half_as_ushort(l0) | ((uint32_t)__half_as_ushort(l1) << 16);
    return (uint32_t)__half_as_ushort(h0) | ((uint32_t)__half_as_ushort(h1) << 16);
}
__device__ __forceinline__ uint32_t packq(float x0, float x1) {
    return (uint32_t)__half_as_ushort(__float2half_rn(x0)) |
           ((uint32_t)__half_as_ushort(__float2half_rn(x1)) << 16);
}

// ---------------- tensor-core GEMM: C[M,N] = A[M,K] @ Bt^T -------------------
// A: [M,K] fp32 (MODE 0) or att(elP,erP,stat) on the fly (MODE 1; MODE 2 also
// writes fp32 att to attOut — requires gridDim.x == 1). Bt: fp16 [N][K].
// CTA tile 128x128, BK=32, 8 warps (2m x 4n), warp tile 64x32, m16n8k16.
// A split exact (ahi+alo). TERMS=2: B quantized -> ahi*b + alo*b.
// TERMS=3: B exact hi/lo -> ahi*bhi + alo*bhi + ahi*blo (error ~2^-22).
// EPI: 0 none, 1 ELU. 2 CTAs/SM, SW64 smem.
// TR: 0 = write fp32 C. 1/2 = write transposed fp16 plane (htQ, [b][feat][node])
// + el/er dual-dot partials (TR 1: part = n0>>7; TR 2: part0 = value, part1 = 0).
template <int MODE, int EPI, int TR, int TERMS>
__global__ void __launch_bounds__(256, 2)
tc_gemm(const float* __restrict__ A,
        const __half* __restrict__ Bq, const __half* __restrict__ Bl,
        float* __restrict__ C, int N, int K,
        long long sA, long long sBt, long long sC,
        const float* __restrict__ elP, const float* __restrict__ erP,
        const float* __restrict__ stat, float* __restrict__ attOut,
        const float* __restrict__ av, int NF,
        __half* __restrict__ htQ,
        float* __restrict__ elO, float* __restrict__ erO)
{
    extern __shared__ char smem[];
    // per buffer: A_hi 8K | A_lo 8K | B 8K [| B_lo 8K] ; two buffers
    constexpr int BUF = (TERMS == 3) ? 32768 : 24576;
    constexpr int OAH = 0, OAL = 8192, OBQ = 16384, OBL = 24576;

    const int bz = blockIdx.z;
    if (MODE == 0) A += (long long)bz * sA;
    Bq += (long long)bz * sBt;
    if (TERMS == 3) Bl += (long long)bz * sBt;
    if (TR == 0) C += (long long)bz * sC;

    const int m0 = blockIdx.y * 128;
    const int n0 = blockIdx.x * 128;
    const int tid  = threadIdx.x;
    const int warp = tid >> 5, lane = tid & 31;
    const int mw = (warp >> 2) * 64;     // warp row base in tile
    const int nw = (warp & 3) * 32;      // warp col base in tile

    const uint32_t sb = smem_u32(smem);

    // A producer mapping: row = tid>>1 (0..127), 16-col half (tid&1)
    const int ar = tid >> 1;
    const int ac = (tid & 1) * 16;
    float elv = 0.f, mn = 0.f, kk = 0.f;
    if (MODE != 0) {
        elv = elP[bz * NN + m0 + ar] + elP[TOT + bz * NN + m0 + ar];
        mn  = stat[bz * 2 + 0];
        kk  = stat[bz * 2 + 1];
    }

    float va[16];

    auto produce_load = [&](int c) {
        const int k0 = c << 5;
        if (MODE == 0) {
            const float4* Sp = (const float4*)(A + (long long)(m0 + ar) * K + k0 + ac);
#pragma unroll
            for (int q = 0; q < 4; q++) {
                float4 f = Sp[q];
                va[q * 4 + 0] = f.x; va[q * 4 + 1] = f.y;
                va[q * 4 + 2] = f.z; va[q * 4 + 3] = f.w;
            }
        } else {
            const float4* E0 = (const float4*)(erP + bz * NN + k0 + ac);
            const float4* E1 = (const float4*)(erP + TOT + bz * NN + k0 + ac);
#pragma unroll
            for (int q = 0; q < 4; q++) {
                float4 f = E0[q];
                float4 g = E1[q];
                va[q * 4 + 0] = f.x + g.x; va[q * 4 + 1] = f.y + g.y;
                va[q * 4 + 2] = f.z + g.z; va[q * 4 + 3] = f.w + g.w;
            }
        }
    };

    auto produce_B = [&](int c, int buf) {
        const int k0 = c << 5;
        const uint32_t dB = sb + buf * BUF + OBQ;
        const uint32_t dL = sb + buf * BUF + OBL;
#pragma unroll
        for (int rep = 0; rep < 2; rep++) {
            int idx = tid + rep * 256;         // 0..511 granules
            int row = idx >> 2, q = idx & 3;
            uint32_t so = sw64(row * 64 + q * 16);
            cpasync16(dB + so, Bq + (long long)(n0 + row) * K + k0 + q * 8);
            if (TERMS == 3)
                cpasync16(dL + so, Bl + (long long)(n0 + row) * K + k0 + q * 8);
        }
        CP_COMMIT();
    };

    auto produce_store = [&](int c, int buf) {
        char* base = smem + buf * BUF;
        if (MODE != 0) {
#pragma unroll
            for (int e = 0; e < 16; e++) va[e] = attf(elv + va[e], mn, kk);
            if (MODE == 2) {
                const int k0 = c << 5;
                float4* Op = (float4*)(attOut + (long long)bz * NN * NN +
                                       (long long)(m0 + ar) * NN + k0 + ac);
#pragma unroll
                for (int q = 0; q < 4; q++)
                    Op[q] = make_float4(va[q * 4], va[q * 4 + 1], va[q * 4 + 2], va[q * 4 + 3]);
            }
        }
#pragma unroll
        for (int g = 0; g < 2; g++) {
            uint4 hq, lq;
            uint32_t* hw = (uint32_t*)&hq;
            uint32_t* lw = (uint32_t*)&lq;
#pragma unroll
            for (int e = 0; e < 4; e++)
                hw[e] = packsplit(va[g * 8 + e * 2], va[g * 8 + e * 2 + 1], lw[e]);
            uint32_t so = sw64(ar * 64 + ac * 2 + g * 16);
            *(uint4*)(base + OAH + so) = hq;
            *(uint4*)(base + OAL + so) = lq;
        }
    };

    float acc[4][4][4] = {};

    auto consume = [&](int buf) {
        const uint32_t aH = sb + buf * BUF + OAH;
        const uint32_t aL = sb + buf * BUF + OAL;
        const uint32_t bB = sb + buf * BUF + OBQ;
        const uint32_t bLo = sb + buf * BUF + OBL;
        const uint32_t aRow = (lane & 15);
        const uint32_t aKof = (lane >> 4) * 16;
        const uint32_t bRow = (lane & 7);
        const uint32_t bKof = ((lane >> 3) & 1) * 16;
#pragma unroll
        for (int ks = 0; ks < 2; ks++) {
            const uint32_t kb = ks * 32;       // byte col of k0+ks*16
            unsigned ah[4][4], al[4][4], bh[4][2], bl[4][2];
#pragma unroll
            for (int mt = 0; mt < 4; mt++) {
                uint32_t off = sw64((mw + mt * 16 + aRow) * 64 + kb + aKof);
                ldx4(ah[mt], aH + off);
                ldx4(al[mt], aL + off);
            }
#pragma unroll
            for (int nt = 0; nt < 4; nt++) {
                uint32_t off = sw64((nw + nt * 8 + bRow) * 64 + kb + bKof);
                ldx2(bh[nt], bB + off);
                if (TERMS == 3) ldx2(bl[nt], bLo + off);
            }
            // term-major: 16 independent MMAs between same-acc reuses
#pragma unroll
            for (int mt = 0; mt < 4; mt++)
#pragma unroll
                for (int nt = 0; nt < 4; nt++)
                    mma16816(acc[mt][nt], ah[mt], bh[nt]);
#pragma unroll
            for (int mt = 0; mt < 4; mt++)
#pragma unroll
                for (int nt = 0; nt < 4; nt++)
                    mma16816(acc[mt][nt], al[mt], bh[nt]);
            if (TERMS == 3) {
#pragma unroll
                for (int mt = 0; mt < 4; mt++)
#pragma unroll
                    for (int nt = 0; nt < 4; nt++)
                        mma16816(acc[mt][nt], ah[mt], bl[nt]);
            }
        }
    };

    const int nCh = K >> 5;
    // prologue
    produce_load(0);
    produce_B(0, 0);
    produce_store(0, 0);
    CP_WAIT0();
    __syncthreads();

    int buf = 0;
    for (int c = 0; c < nCh; c++) {
        const bool more = (c + 1 < nCh);
        if (more) {
            produce_load(c + 1);       // LDG issued; latency covered by consume
            produce_B(c + 1, buf ^ 1); // cp.async, off-thread
        }
        consume(buf);
        if (more) produce_store(c + 1, buf ^ 1);
        CP_WAIT0();
        __syncthreads();
        buf ^= 1;
    }

    // ---- epilogue ----
    const int r0 = lane >> 2;
    const int cc = (lane & 3) * 2;
    if (TR == 0) {
#pragma unroll
        for (int mt = 0; mt < 4; mt++) {
#pragma unroll
            for (int nt = 0; nt < 4; nt++) {
                float* a4 = acc[mt][nt];
                if (EPI == 1) {
#pragma unroll
                    for (int e = 0; e < 4; e++)
                        a4[e] = a4[e] > 0.f ? a4[e] : (__expf(a4[e]) - 1.f);
                }
                const int col = n0 + nw + nt * 8 + cc;
                const int row = m0 + mw + mt * 16 + r0;
                *(float2*)&C[(long long)row * N + col]       = make_float2(a4[0], a4[1]);
                *(float2*)&C[(long long)(row + 8) * N + col] = make_float2(a4[2], a4[3]);
            }
        }
    } else {
        // stage tile to smem fp32 [128][129]
        __syncthreads();
        float* ts = (float*)smem;
#pragma unroll
        for (int mt = 0; mt < 4; mt++) {
#pragma unroll
            for (int nt = 0; nt < 4; nt++) {
                float* a4 = acc[mt][nt];
                const int row = mw + mt * 16 + r0;
                const int col = nw + nt * 8 + cc;
                ts[row * 129 + col]           = a4[0];
                ts[row * 129 + col + 1]       = a4[1];
                ts[(row + 8) * 129 + col]     = a4[2];
                ts[(row + 8) * 129 + col + 1] = a4[3];
            }
        }
        __syncthreads();
        // el/er partial dual-dot: thread = (row, feat-half)
        {
            const int row = tid >> 1;
            const int hf  = tid & 1;
            const float* tr = ts + row * 129 + hf * 64;
            const float* aLp = av + n0 + hf * 64;
            const float* aRp = av + NF + n0 + hf * 64;
            float sl = 0.f, sr = 0.f;
#pragma unroll
            for (int f = 0; f < 64; f++) {
                float v = tr[f];
                sl = fmaf(v, aLp[f], sl);
                sr = fmaf(v, aRp[f], sr);
            }
            sl += __shfl_xor_sync(0xFFFFFFFFu, sl, 1);
            sr += __shfl_xor_sync(0xFFFFFFFFu, sr, 1);
            if (hf == 0) {
                const int grow = m0 + row;
                if (TR == 1) {
                    const int part = n0 >> 7;
                    elO[part * TOT + grow] = sl;
                    erO[part * TOT + grow] = sr;
                } else {
                    elO[grow] = sl; elO[TOT + grow] = 0.f;
                    erO[grow] = sr; erO[TOT + grow] = 0.f;
                }
            }
        }
        // transposed fp16 write: thread = (feat, node-half)
        {
            const int f  = tid >> 1;
            const int hf = tid & 1;
            const int b  = m0 >> 10;
            const int node0 = (m0 & 1023) + hf * 64;
            __half* dh = htQ + ((long long)(b * NF + n0 + f) * NN) + node0;
#pragma unroll
            for (int i0 = 0; i0 < 64; i0 += 8) {
                uint4 hq;
                uint32_t* hw = (uint32_t*)&hq;
#pragma unroll
                for (int e = 0; e < 4; e++) {
                    float x0 = ts[(hf * 64 + i0 + e * 2)     * 129 + f];
                    float x1 = ts[(hf * 64 + i0 + e * 2 + 1) * 129 + f];
                    hw[e] = packq(x0, x1);
                }
                *(uint4*)(dh + i0) = hq;
            }
        }
    }
}

// ---------------- transpose + fp16 exact split (weights) --------------------
__global__ void prepT(const float* __restrict__ src, __half* __restrict__ dhi,
                      __half* __restrict__ dlo, int R, int Cc)
{
    __shared__ float t[32][33];
    const int c0 = blockIdx.x * 32;
    const int r0 = blockIdx.y * 32;
    const int tx = threadIdx.x, ty = threadIdx.y;
#pragma unroll
    for (int i = ty; i < 32; i += 8)
        t[i][tx] = src[(long long)(r0 + i) * Cc + c0 + tx];
    __syncthreads();
#pragma unroll
    for (int i = ty; i < 32; i += 8) {
        float v = t[tx][i];
        __half h = __float2half_rn(v);
        float rr = v - __half2float(h);
        dhi[(long long)(c0 + i) * R + r0 + tx] = h;
        dlo[(long long)(c0 + i) * R + r0 + tx] = __float2half_rn(rr);
    }
}

// ---------------- per-batch min/max of separable e --------------------------
__global__ void minmax_stats(const float* __restrict__ elP, const float* __restrict__ erP,
                             float* __restrict__ stat)
{
    const int b = blockIdx.x;
    const int tid = threadIdx.x;
    float mnl = 1e30f, mxl = -1e30f, mnr = 1e30f, mxr = -1e30f;
    for (int i = tid; i < NN; i += 256) {
        float l = elP[b * NN + i] + elP[TOT + b * NN + i];
        float r = erP[b * NN + i] + erP[TOT + b * NN + i];
        mnl = fminf(mnl, l); mxl = fmaxf(mxl, l);
        mnr = fminf(mnr, r); mxr = fmaxf(mxr, r);
    }
#pragma unroll
    for (int o = 16; o; o >>= 1) {
        mnl = fminf(mnl, __shfl_xor_sync(0xFFFFFFFFu, mnl, o));
        mxl = fmaxf(mxl, __shfl_xor_sync(0xFFFFFFFFu, mxl, o));
        mnr = fminf(mnr, __shfl_xor_sync(0xFFFFFFFFu, mnr, o));
        mxr = fmaxf(mxr, __shfl_xor_sync(0xFFFFFFFFu, mxr, o));
    }
    __shared__ float s[4][8];
    const int w = tid >> 5, lane = tid & 31;
    if (lane == 0) { s[0][w] = mnl; s[1][w] = mxl; s[2][w] = mnr; s[3][w] = mxr; }
    __syncthreads();
    if (tid == 0) {
        float a0 = s[0][0], a1 = s[1][0], a2 = s[2][0], a3 = s[3][0];
#pragma unroll
        for (int i = 1; i < 8; i++) {
            a0 = fminf(a0, s[0][i]); a1 = fmaxf(a1, s[1][i]);
            a2 = fminf(a2, s[2][i]); a3 = fmaxf(a3, s[3][i]);
        }
        float lo = a0 + a2, hi = a1 + a3;
        float mn = lo >= 0.f ? lo : 0.01f * lo;
        float mx = hi >= 0.f ? hi : 0.01f * hi;
        stat[b * 2 + 0] = mn;
        stat[b * 2 + 1] = 30.f / (mx - mn);
    }
}

// ---------------- gv = g2 @ Wg ----------------------------------------------
__global__ void gv_kernel(const float* __restrict__ g2, const float* __restrict__ Wg,
                          float* __restrict__ gv)
{
    const int row  = (blockIdx.x * blockDim.x + threadIdx.x) >> 5;
    const int lane = threadIdx.x & 31;
    const float* gp = g2 + (long long)row * H2_;
    float s = fmaf(gp[lane], Wg[lane], gp[lane + 32] * Wg[lane + 32]);
    s = fmaf(gp[lane + 64], Wg[lane + 64], s);
    s = fmaf(gp[lane + 96], Wg[lane + 96], s);
#pragma unroll
    for (int o = 16; o; o >>= 1) s += __shfl_xor_sync(0xFFFFFFFFu, s, o);
    if (lane == 0) gv[row] = s;
}

// ---------------- out = leaky(fc2 @ gv + bg) ----------------------------------
__global__ void z_kernel(const float* __restrict__ fc2, const float* __restrict__ gv,
                         const float* __restrict__ bg, float* __restrict__ out)
{
    const int row  = (blockIdx.x * blockDim.x + threadIdx.x) >> 5;
    const int lane = threadIdx.x & 31;
    const int b = row >> 10;
    const float* fr = fc2 + (long long)row * NN;
    const float* gr = gv + b * NN;
    float s = 0.f;
#pragma unroll
    for (int j = lane * 4; j < NN; j += 128) {
        float4 f = *(const float4*)&fr[j];
        float4 g = *(const float4*)&gr[j];
        s = fmaf(f.x, g.x, s); s = fmaf(f.y, g.y, s);
        s = fmaf(f.z, g.z, s); s = fmaf(f.w, g.w, s);
    }
#pragma unroll
    for (int o = 16; o; o >>= 1) s += __shfl_xor_sync(0xFFFFFFFFu, s, o);
    if (lane == 0) {
        float z = s + bg[0];
        out[row] = z >= 0.f ? z : 0.01f * z;
    }
}

// ---------------------------------------------------------------------------
template <typename T>
static T* sym_p(const void* s)
{
    void* p = nullptr;
    cudaGetSymbolAddress(&p, s);
    return (T*)p;
}

extern "C" void kernel_launch(void* const* d_in, const int* in_sizes, int n_in,
                              void* d_out, int out_size)
{
    const float* x  = (const float*)d_in[0];
    const float* W1 = (const float*)d_in[2];
    const float* a1 = (const float*)d_in[3];
    const float* W2 = (const float*)d_in[4];
    const float* a2 = (const float*)d_in[5];
    const float* Wg = (const float*)d_in[6];
    const float* bg = (const float*)d_in[7];

    float* out = (float*)d_out;
    float* fc2 = out + (long long)B_ * NN;
    float* g2  = fc2 + (long long)B_ * NN * NN;

    float* g1   = sym_p<float>(d_g1);
    float* elP  = sym_p<float>(d_elP);
    float* erP  = sym_p<float>(d_erP);
    float* stat = sym_p<float>(d_stat);
    float* gv   = sym_p<float>(d_gv);
    __half* ht1  = sym_p<__half>(d_ht1);
    __half* ht2  = sym_p<__half>(d_ht2);
    __half* wt1h = sym_p<__half>(d_wt1_hi);
    __half* wt1l = sym_p<__half>(d_wt1_lo);
    __half* wt2h = sym_p<__half>(d_wt2_hi);
    __half* wt2l = sym_p<__half>(d_wt2_lo);

    const int SMB2   = 2 * 24576;           // 48 KB (2-term)
    const int SMB_TR = 128 * 129 * 4 + 512; // 66.5 KB (3-term TR: max(64K, staging))
    cudaFuncSetAttribute(tc_gemm<0, 0, 1, 3>, cudaFuncAttributeMaxDynamicSharedMemorySize, SMB_TR);
    cudaFuncSetAttribute(tc_gemm<1, 1, 0, 2>, cudaFuncAttributeMaxDynamicSharedMemorySize, SMB2);
    cudaFuncSetAttribute(tc_gemm<0, 0, 2, 3>, cudaFuncAttributeMaxDynamicSharedMemorySize, SMB_TR);
    cudaFuncSetAttribute(tc_gemm<2, 0, 0, 2>, cudaFuncAttributeMaxDynamicSharedMemorySize, SMB2);

    const int rowsTot = B_ * NN;              // 32768
    const dim3 tp(32, 8);

    // ===== weight preps (tiny, exact hi/lo split) =====
    prepT<<<dim3(H1_ / 32, FIN / 32, 1), tp>>>(W1, wt1h, wt1l, FIN, H1_);
    prepT<<<dim3(H2_ / 32, H1_ / 32, 1), tp>>>(W2, wt2h, wt2l, H1_, H2_);

    // ===== Layer 1 =====
    // h1 = x @ W1 (3-term, exact); fused: writes ht1 (transposed fp16) + el/er parts
    tc_gemm<0, 0, 1, 3><<<dim3(H1_ / 128, rowsTot / 128, 1), 256, SMB_TR>>>(
        x, wt1h, wt1l, nullptr, H1_, FIN, 0, 0, 0,
        nullptr, nullptr, nullptr, nullptr, a1, H1_, ht1, elP, erP);
    minmax_stats<<<B_, 256>>>(elP, erP, stat);
    // g1 = elu(att1 @ h1), att1 on the fly (2-term)
    tc_gemm<1, 1, 0, 2><<<dim3(H1_ / 128, NN / 128, B_), 256, SMB2>>>(
        nullptr, ht1, nullptr, g1, H1_, NN,
        0, (long long)H1_ * NN, (long long)NN * H1_,
        elP, erP, stat, nullptr, nullptr, 0, nullptr, nullptr, nullptr);

    // ===== Layer 2 =====
    // h2 = g1 @ W2 (3-term, exact); fused: writes ht2 + el/er (part1 zeroed)
    tc_gemm<0, 0, 2, 3><<<dim3(H2_ / 128, rowsTot / 128, 1), 256, SMB_TR>>>(
        g1, wt2h, wt2l, nullptr, H2_, H1_, 0, 0, 0,
        nullptr, nullptr, nullptr, nullptr, a2, H2_, ht2, elP, erP);
    minmax_stats<<<B_, 256>>>(elP, erP, stat);
    // g2 = fc2 @ h2 (2-term); fc2 written on the fly (gridDim.x == 1)
    tc_gemm<2, 0, 0, 2><<<dim3(H2_ / 128, NN / 128, B_), 256, SMB2>>>(
        nullptr, ht2, nullptr, g2, H2_, NN,
        0, (long long)H2_ * NN, (long long)NN * H2_,
        elP, erP, stat, fc2, nullptr, 0, nullptr, nullptr, nullptr);

    // ===== Head: out = leaky(fc2 @ (g2 @ Wg) + bg) =====
    gv_kernel<<<rowsTot / 8, 256>>>(g2, Wg, gv);
    z_kernel<<<rowsTot / 8, 256>>>(fc2, gv, bg, out);
}

// round 13
// speedup vs baseline: 1.2462x; 1.1385x over previous
#include <cuda_runtime.h>
#include <cuda_fp16.h>
#include <math.h>
#include <stdint.h>

#define B_   32
#define NN   1024
#define FIN  512
#define H1_  256
#define H2_  128
#define TOT  32768

// ---------------- scratch (device globals; no allocation allowed) ----------
__device__ float d_g1[B_ * NN * H1_];
__device__ float d_elP[2 * TOT];
__device__ float d_erP[2 * TOT];
__device__ float d_stat[B_ * 2];
__device__ float d_gv[B_ * NN];
// transposed fp16 B operands ([N][K] layout)
__device__ __half d_ht1[B_ * H1_ * NN];     // quantized single plane
__device__ __half d_ht2[B_ * H2_ * NN];     // quantized single plane
__device__ __half d_wt1_hi[H1_ * FIN];      // exact hi/lo split
__device__ __half d_wt1_lo[H1_ * FIN];
__device__ __half d_wt2_hi[H2_ * H1_];
__device__ __half d_wt2_lo[H2_ * H1_];

__device__ __forceinline__ uint32_t smem_u32(const void* p) {
    return (uint32_t)__cvta_generic_to_shared(p);
}
__device__ __forceinline__ uint32_t sw64(uint32_t off) {
    return off ^ ((off >> 3) & 0x30);
}
__device__ __forceinline__ float attf(float x, float mn, float kk) {
    float lr = x >= 0.f ? x : 0.01f * x;
    return 1.f / (1.f + __expf(-(fmaf(lr - mn, kk, -20.f))));
}
__device__ __forceinline__ void ldx4(unsigned* r, uint32_t addr) {
    asm volatile("ldmatrix.sync.aligned.m8n8.x4.shared.b16 {%0,%1,%2,%3}, [%4];"
                 : "=r"(r[0]), "=r"(r[1]), "=r"(r[2]), "=r"(r[3]) : "r"(addr));
}
__device__ __forceinline__ void ldx2(unsigned* r, uint32_t addr) {
    asm volatile("ldmatrix.sync.aligned.m8n8.x2.shared.b16 {%0,%1}, [%2];"
                 : "=r"(r[0]), "=r"(r[1]) : "r"(addr));
}
__device__ __forceinline__ void mma16816(float* c, const unsigned* a, const unsigned* b) {
    asm volatile(
        "mma.sync.aligned.m16n8k16.row.col.f32.f16.f16.f32 "
        "{%0,%1,%2,%3}, {%4,%5,%6,%7}, {%8,%9}, {%0,%1,%2,%3};"
        : "+f"(c[0]), "+f"(c[1]), "+f"(c[2]), "+f"(c[3])
        : "r"(a[0]), "r"(a[1]), "r"(a[2]), "r"(a[3]), "r"(b[0]), "r"(b[1]));
}
__device__ __forceinline__ void cpasync16(uint32_t saddr, const void* gptr) {
    asm volatile("cp.async.cg.shared.global [%0], [%1], 16;"
                 :: "r"(saddr), "l"(gptr) : "memory");
}
#define CP_COMMIT() asm volatile("cp.async.commit_group;" ::: "memory")
#define CP_WAIT0()  asm volatile("cp.async.wait_group 0;" ::: "memory")

// exact split: x = hi + lo (both fp16); returns packed hi pair, writes lo pair
__device__ __forceinline__ uint32_t packsplit(float x0, float x1, uint32_t& lo) {
    __half h0 = __float2half_rn(x0), h1 = __float2half_rn(x1);
    float r0 = x0 - __half2float(h0);
    float r1 = x1 - __half2float(h1);
    __half l0 = __float2half_rn(r0), l1 = __float2half_rn(r1);
    lo = (uint32_t)__half_as_ushort(l0) | ((uint32_t)__half_as_ushort(l1) << 16);
    return (uint32_t)__half_as_ushort(h0) | ((uint32_t)__half_as_ushort(h1) << 16);
}
__device__ __forceinline__ uint32_t packq(float x0, float x1) {
    return (uint32_t)__half_as_ushort(__float2half_rn(x0)) |
           ((uint32_t)__half_as_ushort(__float2half_rn(x1)) << 16);
}

// ---------------- tensor-core GEMM: C[M,N] = A[M,K] @ Bt^T -------------------
// A: [M,K] fp32 (MODE 0) or att(elP,erP,stat) on the fly (MODE 1; MODE 2 also
// writes fp32 att to attOut — requires gridDim.x == 1). Bt: fp16 [N][K].
// CTA tile 128x128, BK=32, 8 warps (2m x 4n), warp tile 64x32, m16n8k16.
// TERMS=1: A quantized single plane, B quantized -> aq*b.
// TERMS=3: A exact split, B exact hi/lo -> ahi*bhi + alo*bhi + ahi*blo.
// EPI: 0 none, 1 ELU. 2 CTAs/SM, SW64 smem.
// TR: 0 = write fp32 C. 1/2 = write transposed fp16 plane (htQ, [b][feat][node])
// + el/er dual-dot partials (TR 1: part = n0>>7; TR 2: part0 = value, part1 = 0).
template <int MODE, int EPI, int TR, int TERMS>
__global__ void __launch_bounds__(256, 2)
tc_gemm(const float* __restrict__ A,
        const __half* __restrict__ Bq, const __half* __restrict__ Bl,
        float* __restrict__ C, int N, int K,
        long long sA, long long sBt, long long sC,
        const float* __restrict__ elP, const float* __restrict__ erP,
        const float* __restrict__ stat, float* __restrict__ attOut,
        const float* __restrict__ av, int NF,
        __half* __restrict__ htQ,
        float* __restrict__ elO, float* __restrict__ erO)
{
    extern __shared__ char smem[];
    // per buffer: TERMS==1: A 8K | B 8K = 16K.  TERMS==3: Ahi 8K | Alo 8K | Bhi 8K | Blo 8K = 32K
    constexpr int BUF = (TERMS == 3) ? 32768 : 16384;
    constexpr int OAH = 0;
    constexpr int OAL = 8192;                              // TERMS==3 only
    constexpr int OBQ = (TERMS == 3) ? 16384 : 8192;
    constexpr int OBL = 24576;                             // TERMS==3 only

    const int bz = blockIdx.z;
    if (MODE == 0) A += (long long)bz * sA;
    Bq += (long long)bz * sBt;
    if (TERMS == 3) Bl += (long long)bz * sBt;
    if (TR == 0) C += (long long)bz * sC;

    const int m0 = blockIdx.y * 128;
    const int n0 = blockIdx.x * 128;
    const int tid  = threadIdx.x;
    const int warp = tid >> 5, lane = tid & 31;
    const int mw = (warp >> 2) * 64;     // warp row base in tile
    const int nw = (warp & 3) * 32;      // warp col base in tile

    const uint32_t sb = smem_u32(smem);

    // A producer mapping: row = tid>>1 (0..127), 16-col half (tid&1)
    const int ar = tid >> 1;
    const int ac = (tid & 1) * 16;
    float elv = 0.f, mn = 0.f, kk = 0.f;
    if (MODE != 0) {
        elv = elP[bz * NN + m0 + ar] + elP[TOT + bz * NN + m0 + ar];
        mn  = stat[bz * 2 + 0];
        kk  = stat[bz * 2 + 1];
    }

    float va[16];

    auto produce_load = [&](int c) {
        const int k0 = c << 5;
        if (MODE == 0) {
            const float4* Sp = (const float4*)(A + (long long)(m0 + ar) * K + k0 + ac);
#pragma unroll
            for (int q = 0; q < 4; q++) {
                float4 f = Sp[q];
                va[q * 4 + 0] = f.x; va[q * 4 + 1] = f.y;
                va[q * 4 + 2] = f.z; va[q * 4 + 3] = f.w;
            }
        } else {
            const float4* E0 = (const float4*)(erP + bz * NN + k0 + ac);
            const float4* E1 = (const float4*)(erP + TOT + bz * NN + k0 + ac);
#pragma unroll
            for (int q = 0; q < 4; q++) {
                float4 f = E0[q];
                float4 g = E1[q];
                va[q * 4 + 0] = f.x + g.x; va[q * 4 + 1] = f.y + g.y;
                va[q * 4 + 2] = f.z + g.z; va[q * 4 + 3] = f.w + g.w;
            }
        }
    };

    auto produce_B = [&](int c, int buf) {
        const int k0 = c << 5;
        const uint32_t dB = sb + buf * BUF + OBQ;
        const uint32_t dL = sb + buf * BUF + OBL;
#pragma unroll
        for (int rep = 0; rep < 2; rep++) {
            int idx = tid + rep * 256;         // 0..511 granules
            int row = idx >> 2, q = idx & 3;
            uint32_t so = sw64(row * 64 + q * 16);
            cpasync16(dB + so, Bq + (long long)(n0 + row) * K + k0 + q * 8);
            if (TERMS == 3)
                cpasync16(dL + so, Bl + (long long)(n0 + row) * K + k0 + q * 8);
        }
        CP_COMMIT();
    };

    auto produce_store = [&](int c, int buf) {
        char* base = smem + buf * BUF;
        if (MODE != 0) {
#pragma unroll
            for (int e = 0; e < 16; e++) va[e] = attf(elv + va[e], mn, kk);
            if (MODE == 2) {
                const int k0 = c << 5;
                float4* Op = (float4*)(attOut + (long long)bz * NN * NN +
                                       (long long)(m0 + ar) * NN + k0 + ac);
#pragma unroll
                for (int q = 0; q < 4; q++)
                    Op[q] = make_float4(va[q * 4], va[q * 4 + 1], va[q * 4 + 2], va[q * 4 + 3]);
            }
        }
#pragma unroll
        for (int g = 0; g < 2; g++) {
            uint32_t so = sw64(ar * 64 + ac * 2 + g * 16);
            if (TERMS == 1) {
                uint4 hq;
                uint32_t* hw = (uint32_t*)&hq;
#pragma unroll
                for (int e = 0; e < 4; e++)
                    hw[e] = packq(va[g * 8 + e * 2], va[g * 8 + e * 2 + 1]);
                *(uint4*)(base + OAH + so) = hq;
            } else {
                uint4 hq, lq;
                uint32_t* hw = (uint32_t*)&hq;
                uint32_t* lw = (uint32_t*)&lq;
#pragma unroll
                for (int e = 0; e < 4; e++)
                    hw[e] = packsplit(va[g * 8 + e * 2], va[g * 8 + e * 2 + 1], lw[e]);
                *(uint4*)(base + OAH + so) = hq;
                *(uint4*)(base + OAL + so) = lq;
            }
        }
    };

    float acc[4][4][4] = {};

    auto consume = [&](int buf) {
        const uint32_t aH = sb + buf * BUF + OAH;
        const uint32_t aL = sb + buf * BUF + OAL;
        const uint32_t bB = sb + buf * BUF + OBQ;
        const uint32_t bLo = sb + buf * BUF + OBL;
        const uint32_t aRow = (lane & 15);
        const uint32_t aKof = (lane >> 4) * 16;
        const uint32_t bRow = (lane & 7);
        const uint32_t bKof = ((lane >> 3) & 1) * 16;
#pragma unroll
        for (int ks = 0; ks < 2; ks++) {
            const uint32_t kb = ks * 32;       // byte col of k0+ks*16
            unsigned ah[4][4], al[4][4], bh[4][2], bl[4][2];
#pragma unroll
            for (int mt = 0; mt < 4; mt++) {
                uint32_t off = sw64((mw + mt * 16 + aRow) * 64 + kb + aKof);
                ldx4(ah[mt], aH + off);
                if (TERMS >= 2) ldx4(al[mt], aL + off);
            }
#pragma unroll
            for (int nt = 0; nt < 4; nt++) {
                uint32_t off = sw64((nw + nt * 8 + bRow) * 64 + kb + bKof);
                ldx2(bh[nt], bB + off);
                if (TERMS == 3) ldx2(bl[nt], bLo + off);
            }
#pragma unroll
            for (int mt = 0; mt < 4; mt++)
#pragma unroll
                for (int nt = 0; nt < 4; nt++)
                    mma16816(acc[mt][nt], ah[mt], bh[nt]);
            if (TERMS >= 2) {
#pragma unroll
                for (int mt = 0; mt < 4; mt++)
#pragma unroll
                    for (int nt = 0; nt < 4; nt++)
                        mma16816(acc[mt][nt], al[mt], bh[nt]);
            }
            if (TERMS == 3) {
#pragma unroll
                for (int mt = 0; mt < 4; mt++)
#pragma unroll
                    for (int nt = 0; nt < 4; nt++)
                        mma16816(acc[mt][nt], ah[mt], bl[nt]);
            }
        }
    };

    const int nCh = K >> 5;
    // prologue
    produce_load(0);
    produce_B(0, 0);
    produce_store(0, 0);
    CP_WAIT0();
    __syncthreads();

    int buf = 0;
    for (int c = 0; c < nCh; c++) {
        const bool more = (c + 1 < nCh);
        if (more) {
            produce_load(c + 1);       // LDG issued; latency covered by consume
            produce_B(c + 1, buf ^ 1); // cp.async, off-thread
        }
        consume(buf);
        if (more) produce_store(c + 1, buf ^ 1);
        CP_WAIT0();
        __syncthreads();
        buf ^= 1;
    }

    // ---- epilogue ----
    const int r0 = lane >> 2;
    const int cc = (lane & 3) * 2;
    if (TR == 0) {
#pragma unroll
        for (int mt = 0; mt < 4; mt++) {
#pragma unroll
            for (int nt = 0; nt < 4; nt++) {
                float* a4 = acc[mt][nt];
                if (EPI == 1) {
#pragma unroll
                    for (int e = 0; e < 4; e++)
                        a4[e] = a4[e] > 0.f ? a4[e] : (__expf(a4[e]) - 1.f);
                }
                const int col = n0 + nw + nt * 8 + cc;
                const int row = m0 + mw + mt * 16 + r0;
                *(float2*)&C[(long long)row * N + col]       = make_float2(a4[0], a4[1]);
                *(float2*)&C[(long long)(row + 8) * N + col] = make_float2(a4[2], a4[3]);
            }
        }
    } else {
        // stage tile to smem fp32 [128][129]
        __syncthreads();
        float* ts = (float*)smem;
#pragma unroll
        for (int mt = 0; mt < 4; mt++) {
#pragma unroll
            for (int nt = 0; nt < 4; nt++) {
                float* a4 = acc[mt][nt];
                const int row = mw + mt * 16 + r0;
                const int col = nw + nt * 8 + cc;
                ts[row * 129 + col]           = a4[0];
                ts[row * 129 + col + 1]       = a4[1];
                ts[(row + 8) * 129 + col]     = a4[2];
                ts[(row + 8) * 129 + col + 1] = a4[3];
            }
        }
        __syncthreads();
        // el/er partial dual-dot: thread = (row, feat-half)
        {
            const int row = tid >> 1;
            const int hf  = tid & 1;
            const float* tr = ts + row * 129 + hf * 64;
            const float* aLp = av + n0 + hf * 64;
            const float* aRp = av + NF + n0 + hf * 64;
            float sl = 0.f, sr = 0.f;
#pragma unroll
            for (int f = 0; f < 64; f++) {
                float v = tr[f];
                sl = fmaf(v, aLp[f], sl);
                sr = fmaf(v, aRp[f], sr);
            }
            sl += __shfl_xor_sync(0xFFFFFFFFu, sl, 1);
            sr += __shfl_xor_sync(0xFFFFFFFFu, sr, 1);
            if (hf == 0) {
                const int grow = m0 + row;
                if (TR == 1) {
                    const int part = n0 >> 7;
                    elO[part * TOT + grow] = sl;
                    erO[part * TOT + grow] = sr;
                } else {
                    elO[grow] = sl; elO[TOT + grow] = 0.f;
                    erO[grow] = sr; erO[TOT + grow] = 0.f;
                }
            }
        }
        // transposed fp16 write: thread = (feat, node-half)
        {
            const int f  = tid >> 1;
            const int hf = tid & 1;
            const int b  = m0 >> 10;
            const int node0 = (m0 & 1023) + hf * 64;
            __half* dh = htQ + ((long long)(b * NF + n0 + f) * NN) + node0;
#pragma unroll
            for (int i0 = 0; i0 < 64; i0 += 8) {
                uint4 hq;
                uint32_t* hw = (uint32_t*)&hq;
#pragma unroll
                for (int e = 0; e < 4; e++) {
                    float x0 = ts[(hf * 64 + i0 + e * 2)     * 129 + f];
                    float x1 = ts[(hf * 64 + i0 + e * 2 + 1) * 129 + f];
                    hw[e] = packq(x0, x1);
                }
                *(uint4*)(dh + i0) = hq;
            }
        }
    }
}

// ---------------- transpose + fp16 exact split (weights) --------------------
__global__ void prepT(const float* __restrict__ src, __half* __restrict__ dhi,
                      __half* __restrict__ dlo, int R, int Cc)
{
    __shared__ float t[32][33];
    const int c0 = blockIdx.x * 32;
    const int r0 = blockIdx.y * 32;
    const int tx = threadIdx.x, ty = threadIdx.y;
#pragma unroll
    for (int i = ty; i < 32; i += 8)
        t[i][tx] = src[(long long)(r0 + i) * Cc + c0 + tx];
    __syncthreads();
#pragma unroll
    for (int i = ty; i < 32; i += 8) {
        float v = t[tx][i];
        __half h = __float2half_rn(v);
        float rr = v - __half2float(h);
        dhi[(long long)(c0 + i) * R + r0 + tx] = h;
        dlo[(long long)(c0 + i) * R + r0 + tx] = __float2half_rn(rr);
    }
}

// ---------------- per-batch min/max of separable e --------------------------
__global__ void minmax_stats(const float* __restrict__ elP, const float* __restrict__ erP,
                             float* __restrict__ stat)
{
    const int b = blockIdx.x;
    const int tid = threadIdx.x;
    float mnl = 1e30f, mxl = -1e30f, mnr = 1e30f, mxr = -1e30f;
    for (int i = tid; i < NN; i += 256) {
        float l = elP[b * NN + i] + elP[TOT + b * NN + i];
        float r = erP[b * NN + i] + erP[TOT + b * NN + i];
        mnl = fminf(mnl, l); mxl = fmaxf(mxl, l);
        mnr = fminf(mnr, r); mxr = fmaxf(mxr, r);
    }
#pragma unroll
    for (int o = 16; o; o >>= 1) {
        mnl = fminf(mnl, __shfl_xor_sync(0xFFFFFFFFu, mnl, o));
        mxl = fmaxf(mxl, __shfl_xor_sync(0xFFFFFFFFu, mxl, o));
        mnr = fminf(mnr, __shfl_xor_sync(0xFFFFFFFFu, mnr, o));
        mxr = fmaxf(mxr, __shfl_xor_sync(0xFFFFFFFFu, mxr, o));
    }
    __shared__ float s[4][8];
    const int w = tid >> 5, lane = tid & 31;
    if (lane == 0) { s[0][w] = mnl; s[1][w] = mxl; s[2][w] = mnr; s[3][w] = mxr; }
    __syncthreads();
    if (tid == 0) {
        float a0 = s[0][0], a1 = s[1][0], a2 = s[2][0], a3 = s[3][0];
#pragma unroll
        for (int i = 1; i < 8; i++) {
            a0 = fminf(a0, s[0][i]); a1 = fmaxf(a1, s[1][i]);
            a2 = fminf(a2, s[2][i]); a3 = fmaxf(a3, s[3][i]);
        }
        float lo = a0 + a2, hi = a1 + a3;
        float mn = lo >= 0.f ? lo : 0.01f * lo;
        float mx = hi >= 0.f ? hi : 0.01f * hi;
        stat[b * 2 + 0] = mn;
        stat[b * 2 + 1] = 30.f / (mx - mn);
    }
}

// ---------------- gv = g2 @ Wg ----------------------------------------------
__global__ void gv_kernel(const float* __restrict__ g2, const float* __restrict__ Wg,
                          float* __restrict__ gv)
{
    const int row  = (blockIdx.x * blockDim.x + threadIdx.x) >> 5;
    const int lane = threadIdx.x & 31;
    const float* gp = g2 + (long long)row * H2_;
    float s = fmaf(gp[lane], Wg[lane], gp[lane + 32] * Wg[lane + 32]);
    s = fmaf(gp[lane + 64], Wg[lane + 64], s);
    s = fmaf(gp[lane + 96], Wg[lane + 96], s);
#pragma unroll
    for (int o = 16; o; o >>= 1) s += __shfl_xor_sync(0xFFFFFFFFu, s, o);
    if (lane == 0) gv[row] = s;
}

// ---------------- out = leaky(fc2 @ gv + bg) ----------------------------------
__global__ void z_kernel(const float* __restrict__ fc2, const float* __restrict__ gv,
                         const float* __restrict__ bg, float* __restrict__ out)
{
    const int row  = (blockIdx.x * blockDim.x + threadIdx.x) >> 5;
    const int lane = threadIdx.x & 31;
    const int b = row >> 10;
    const float* fr = fc2 + (long long)row * NN;
    const float* gr = gv + b * NN;
    float s = 0.f;
#pragma unroll
    for (int j = lane * 4; j < NN; j += 128) {
        float4 f = *(const float4*)&fr[j];
        float4 g = *(const float4*)&gr[j];
        s = fmaf(f.x, g.x, s); s = fmaf(f.y, g.y, s);
        s = fmaf(f.z, g.z, s); s = fmaf(f.w, g.w, s);
    }
#pragma unroll
    for (int o = 16; o; o >>= 1) s += __shfl_xor_sync(0xFFFFFFFFu, s, o);
    if (lane == 0) {
        float z = s + bg[0];
        out[row] = z >= 0.f ? z : 0.01f * z;
    }
}

// ---------------------------------------------------------------------------
template <typename T>
static T* sym_p(const void* s)
{
    void* p = nullptr;
    cudaGetSymbolAddress(&p, s);
    return (T*)p;
}

extern "C" void kernel_launch(void* const* d_in, const int* in_sizes, int n_in,
                              void* d_out, int out_size)
{
    const float* x  = (const float*)d_in[0];
    const float* W1 = (const float*)d_in[2];
    const float* a1 = (const float*)d_in[3];
    const float* W2 = (const float*)d_in[4];
    const float* a2 = (const float*)d_in[5];
    const float* Wg = (const float*)d_in[6];
    const float* bg = (const float*)d_in[7];

    float* out = (float*)d_out;
    float* fc2 = out + (long long)B_ * NN;
    float* g2  = fc2 + (long long)B_ * NN * NN;

    float* g1   = sym_p<float>(d_g1);
    float* elP  = sym_p<float>(d_elP);
    float* erP  = sym_p<float>(d_erP);
    float* stat = sym_p<float>(d_stat);
    float* gv   = sym_p<float>(d_gv);
    __half* ht1  = sym_p<__half>(d_ht1);
    __half* ht2  = sym_p<__half>(d_ht2);
    __half* wt1h = sym_p<__half>(d_wt1_hi);
    __half* wt1l = sym_p<__half>(d_wt1_lo);
    __half* wt2h = sym_p<__half>(d_wt2_hi);
    __half* wt2l = sym_p<__half>(d_wt2_lo);

    const int SMB1   = 2 * 16384;           // 32 KB (1-term)
    const int SMB_TR = 128 * 129 * 4 + 512; // 66.5 KB (3-term TR: max(64K, staging))
    cudaFuncSetAttribute(tc_gemm<0, 0, 1, 3>, cudaFuncAttributeMaxDynamicSharedMemorySize, SMB_TR);
    cudaFuncSetAttribute(tc_gemm<1, 1, 0, 1>, cudaFuncAttributeMaxDynamicSharedMemorySize, SMB1);
    cudaFuncSetAttribute(tc_gemm<0, 0, 2, 3>, cudaFuncAttributeMaxDynamicSharedMemorySize, SMB_TR);
    cudaFuncSetAttribute(tc_gemm<2, 0, 0, 1>, cudaFuncAttributeMaxDynamicSharedMemorySize, SMB1);

    const int rowsTot = B_ * NN;              // 32768
    const dim3 tp(32, 8);

    // ===== weight preps (tiny, exact hi/lo split) =====
    prepT<<<dim3(H1_ / 32, FIN / 32, 1), tp>>>(W1, wt1h, wt1l, FIN, H1_);
    prepT<<<dim3(H2_ / 32, H1_ / 32, 1), tp>>>(W2, wt2h, wt2l, H1_, H2_);

    // ===== Layer 1 =====
    // h1 = x @ W1 (3-term, exact); fused: writes ht1 (transposed fp16) + el/er parts
    tc_gemm<0, 0, 1, 3><<<dim3(H1_ / 128, rowsTot / 128, 1), 256, SMB_TR>>>(
        x, wt1h, wt1l, nullptr, H1_, FIN, 0, 0, 0,
        nullptr, nullptr, nullptr, nullptr, a1, H1_, ht1, elP, erP);
    minmax_stats<<<B_, 256>>>(elP, erP, stat);
    // g1 = elu(att1 @ h1), att1 on the fly (1-term: att quantized)
    tc_gemm<1, 1, 0, 1><<<dim3(H1_ / 128, NN / 128, B_), 256, SMB1>>>(
        nullptr, ht1, nullptr, g1, H1_, NN,
        0, (long long)H1_ * NN, (long long)NN * H1_,
        elP, erP, stat, nullptr, nullptr, 0, nullptr, nullptr, nullptr);

    // ===== Layer 2 =====
    // h2 = g1 @ W2 (3-term, exact); fused: writes ht2 + el/er (part1 zeroed)
    tc_gemm<0, 0, 2, 3><<<dim3(H2_ / 128, rowsTot / 128, 1), 256, SMB_TR>>>(
        g1, wt2h, wt2l, nullptr, H2_, H1_, 0, 0, 0,
        nullptr, nullptr, nullptr, nullptr, a2, H2_, ht2, elP, erP);
    minmax_stats<<<B_, 256>>>(elP, erP, stat);
    // g2 = fc2 @ h2 (1-term); fc2 written exact fp32 on the fly (gridDim.x == 1)
    tc_gemm<2, 0, 0, 1><<<dim3(H2_ / 128, NN / 128, B_), 256, SMB1>>>(
        nullptr, ht2, nullptr, g2, H2_, NN,
        0, (long long)H2_ * NN, (long long)NN * H2_,
        elP, erP, stat, fc2, nullptr, 0, nullptr, nullptr, nullptr);

    // ===== Head: out = leaky(fc2 @ (g2 @ Wg) + bg) =====
    gv_kernel<<<rowsTot / 8, 256>>>(g2, Wg, gv);
    z_kernel<<<rowsTot / 8, 256>>>(fc2, gv, bg, out);
}

// round 14
// speedup vs baseline: 1.7258x; 1.3848x over previous
#include <cuda_runtime.h>
#include <cuda_fp16.h>
#include <math.h>
#include <stdint.h>

#define B_   32
#define NN   1024
#define FIN  512
#define H1_  256
#define H2_  128
#define TOT  32768

// ---------------- scratch (device globals; no allocation allowed) ----------
__device__ float d_g1[B_ * NN * H1_];
__device__ float d_elP[2 * TOT];
__device__ float d_erP[2 * TOT];
__device__ float d_gv[B_ * NN];
__device__ __half d_att1q[(long long)B_ * NN * NN];   // 67 MB
__device__ __half d_att2q[(long long)B_ * NN * NN];   // 67 MB
// transposed fp16 B operands ([N][K] layout)
__device__ __half d_ht1[B_ * H1_ * NN];
__device__ __half d_ht2[B_ * H2_ * NN];
__device__ __half d_wt1_hi[H1_ * FIN];
__device__ __half d_wt1_lo[H1_ * FIN];
__device__ __half d_wt2_hi[H2_ * H1_];
__device__ __half d_wt2_lo[H2_ * H1_];

__device__ __forceinline__ uint32_t smem_u32(const void* p) {
    return (uint32_t)__cvta_generic_to_shared(p);
}
__device__ __forceinline__ uint32_t sw64(uint32_t off) {
    return off ^ ((off >> 3) & 0x30);
}
__device__ __forceinline__ float fast_sigmoid_z(float z) {
    // sigmoid(z) = 0.5 + 0.5*tanh(z/2); tanh.approx = 1 MUFU op
    float t;
    asm("tanh.approx.f32 %0, %1;" : "=f"(t) : "f"(0.5f * z));
    return fmaf(0.5f, t, 0.5f);
}
__device__ __forceinline__ void ldx4(unsigned* r, uint32_t addr) {
    asm volatile("ldmatrix.sync.aligned.m8n8.x4.shared.b16 {%0,%1,%2,%3}, [%4];"
                 : "=r"(r[0]), "=r"(r[1]), "=r"(r[2]), "=r"(r[3]) : "r"(addr));
}
__device__ __forceinline__ void ldx2(unsigned* r, uint32_t addr) {
    asm volatile("ldmatrix.sync.aligned.m8n8.x2.shared.b16 {%0,%1}, [%2];"
                 : "=r"(r[0]), "=r"(r[1]) : "r"(addr));
}
__device__ __forceinline__ void mma16816(float* c, const unsigned* a, const unsigned* b) {
    asm volatile(
        "mma.sync.aligned.m16n8k16.row.col.f32.f16.f16.f32 "
        "{%0,%1,%2,%3}, {%4,%5,%6,%7}, {%8,%9}, {%0,%1,%2,%3};"
        : "+f"(c[0]), "+f"(c[1]), "+f"(c[2]), "+f"(c[3])
        : "r"(a[0]), "r"(a[1]), "r"(a[2]), "r"(a[3]), "r"(b[0]), "r"(b[1]));
}
__device__ __forceinline__ void cpasync16(uint32_t saddr, const void* gptr) {
    asm volatile("cp.async.cg.shared.global [%0], [%1], 16;"
                 :: "r"(saddr), "l"(gptr) : "memory");
}
#define CP_COMMIT() asm volatile("cp.async.commit_group;" ::: "memory")
#define CP_WAIT0()  asm volatile("cp.async.wait_group 0;" ::: "memory")

__device__ __forceinline__ uint32_t packsplit(float x0, float x1, uint32_t& lo) {
    __half h0 = __float2half_rn(x0), h1 = __float2half_rn(x1);
    float r0 = x0 - __half2float(h0);
    float r1 = x1 - __half2float(h1);
    __half l0 = __float2half_rn(r0), l1 = __float2half_rn(r1);
    lo = (uint32_t)__half_as_ushort(l0) | ((uint32_t)__half_as_ushort(l1) << 16);
    return (uint32_t)__half_as_ushort(h0) | ((uint32_t)__half_as_ushort(h1) << 16);
}
__device__ __forceinline__ uint32_t packq(float x0, float x1) {
    return (uint32_t)__half_as_ushort(__float2half_rn(x0)) |
           ((uint32_t)__half_as_ushort(__float2half_rn(x1)) << 16);
}

// ============ 3-term exact GEMM with transposing epilogue (GEMM1/GEMM3) ======
// C-values never hit gmem as fp32 C; instead epilogue writes:
//   - transposed fp16 plane htQ [b][feat][node]
//   - el/er dual-dot partials (TR 1: part = n0>>7; TR 2: part0 = val, part1 = 0)
// A: [M,K] fp32, exact split; B: fp16 hi/lo exact split. BK=32, 2 CTAs/SM.
template <int TR>
__global__ void __launch_bounds__(256, 2)
tc_gemm3(const float* __restrict__ A,
         const __half* __restrict__ Bhi, const __half* __restrict__ Blo,
         int K,
         const float* __restrict__ av, int NF,
         __half* __restrict__ htQ,
         float* __restrict__ elO, float* __restrict__ erO)
{
    extern __shared__ char smem[];
    constexpr int BUF = 32768;
    constexpr int OAH = 0, OAL = 8192, OBH = 16384, OBL = 24576;

    const int m0 = blockIdx.y * 128;
    const int n0 = blockIdx.x * 128;
    const int tid  = threadIdx.x;
    const int warp = tid >> 5, lane = tid & 31;
    const int mw = (warp >> 2) * 64;
    const int nw = (warp & 3) * 32;
    const uint32_t sb = smem_u32(smem);

    const int ar = tid >> 1;
    const int ac = (tid & 1) * 16;
    float va[16];

    auto produce_load = [&](int c) {
        const int k0 = c << 5;
        const float4* Sp = (const float4*)(A + (long long)(m0 + ar) * K + k0 + ac);
#pragma unroll
        for (int q = 0; q < 4; q++) {
            float4 f = Sp[q];
            va[q * 4 + 0] = f.x; va[q * 4 + 1] = f.y;
            va[q * 4 + 2] = f.z; va[q * 4 + 3] = f.w;
        }
    };
    auto produce_B = [&](int c, int buf) {
        const int k0 = c << 5;
        const uint32_t dH = sb + buf * BUF + OBH;
        const uint32_t dL = sb + buf * BUF + OBL;
#pragma unroll
        for (int rep = 0; rep < 2; rep++) {
            int idx = tid + rep * 256;
            int row = idx >> 2, q = idx & 3;
            uint32_t so = sw64(row * 64 + q * 16);
            cpasync16(dH + so, Bhi + (long long)(n0 + row) * K + k0 + q * 8);
            cpasync16(dL + so, Blo + (long long)(n0 + row) * K + k0 + q * 8);
        }
        CP_COMMIT();
    };
    auto produce_store = [&](int buf) {
        char* base = smem + buf * BUF;
#pragma unroll
        for (int g = 0; g < 2; g++) {
            uint4 hq, lq;
            uint32_t* hw = (uint32_t*)&hq;
            uint32_t* lw = (uint32_t*)&lq;
#pragma unroll
            for (int e = 0; e < 4; e++)
                hw[e] = packsplit(va[g * 8 + e * 2], va[g * 8 + e * 2 + 1], lw[e]);
            uint32_t so = sw64(ar * 64 + ac * 2 + g * 16);
            *(uint4*)(base + OAH + so) = hq;
            *(uint4*)(base + OAL + so) = lq;
        }
    };

    float acc[4][4][4] = {};
    auto consume = [&](int buf) {
        const uint32_t aH = sb + buf * BUF + OAH;
        const uint32_t aL = sb + buf * BUF + OAL;
        const uint32_t bB = sb + buf * BUF + OBH;
        const uint32_t bLo = sb + buf * BUF + OBL;
        const uint32_t aRow = (lane & 15);
        const uint32_t aKof = (lane >> 4) * 16;
        const uint32_t bRow = (lane & 7);
        const uint32_t bKof = ((lane >> 3) & 1) * 16;
#pragma unroll
        for (int ks = 0; ks < 2; ks++) {
            const uint32_t kb = ks * 32;
            unsigned ah[4][4], al[4][4], bh[4][2], bl[4][2];
#pragma unroll
            for (int mt = 0; mt < 4; mt++) {
                uint32_t off = sw64((mw + mt * 16 + aRow) * 64 + kb + aKof);
                ldx4(ah[mt], aH + off);
                ldx4(al[mt], aL + off);
            }
#pragma unroll
            for (int nt = 0; nt < 4; nt++) {
                uint32_t off = sw64((nw + nt * 8 + bRow) * 64 + kb + bKof);
                ldx2(bh[nt], bB + off);
                ldx2(bl[nt], bLo + off);
            }
#pragma unroll
            for (int mt = 0; mt < 4; mt++)
#pragma unroll
                for (int nt = 0; nt < 4; nt++)
                    mma16816(acc[mt][nt], ah[mt], bh[nt]);
#pragma unroll
            for (int mt = 0; mt < 4; mt++)
#pragma unroll
                for (int nt = 0; nt < 4; nt++)
                    mma16816(acc[mt][nt], al[mt], bh[nt]);
#pragma unroll
            for (int mt = 0; mt < 4; mt++)
#pragma unroll
                for (int nt = 0; nt < 4; nt++)
                    mma16816(acc[mt][nt], ah[mt], bl[nt]);
        }
    };

    const int nCh = K >> 5;
    produce_load(0);
    produce_B(0, 0);
    produce_store(0);
    CP_WAIT0();
    __syncthreads();
    int buf = 0;
    for (int c = 0; c < nCh; c++) {
        const bool more = (c + 1 < nCh);
        if (more) {
            produce_load(c + 1);
            produce_B(c + 1, buf ^ 1);
        }
        consume(buf);
        if (more) produce_store(buf ^ 1);
        CP_WAIT0();
        __syncthreads();
        buf ^= 1;
    }

    // ---- transposing epilogue ----
    const int r0 = lane >> 2;
    const int cc = (lane & 3) * 2;
    __syncthreads();
    float* ts = (float*)smem;
#pragma unroll
    for (int mt = 0; mt < 4; mt++) {
#pragma unroll
        for (int nt = 0; nt < 4; nt++) {
            float* a4 = acc[mt][nt];
            const int row = mw + mt * 16 + r0;
            const int col = nw + nt * 8 + cc;
            ts[row * 129 + col]           = a4[0];
            ts[row * 129 + col + 1]       = a4[1];
            ts[(row + 8) * 129 + col]     = a4[2];
            ts[(row + 8) * 129 + col + 1] = a4[3];
        }
    }
    __syncthreads();
    {
        const int row = tid >> 1;
        const int hf  = tid & 1;
        const float* tr = ts + row * 129 + hf * 64;
        const float* aLp = av + n0 + hf * 64;
        const float* aRp = av + NF + n0 + hf * 64;
        float sl = 0.f, sr = 0.f;
#pragma unroll
        for (int f = 0; f < 64; f++) {
            float v = tr[f];
            sl = fmaf(v, aLp[f], sl);
            sr = fmaf(v, aRp[f], sr);
        }
        sl += __shfl_xor_sync(0xFFFFFFFFu, sl, 1);
        sr += __shfl_xor_sync(0xFFFFFFFFu, sr, 1);
        if (hf == 0) {
            const int grow = m0 + row;
            if (TR == 1) {
                const int part = n0 >> 7;
                elO[part * TOT + grow] = sl;
                erO[part * TOT + grow] = sr;
            } else {
                elO[grow] = sl; elO[TOT + grow] = 0.f;
                erO[grow] = sr; erO[TOT + grow] = 0.f;
            }
        }
    }
    {
        const int f  = tid >> 1;
        const int hf = tid & 1;
        const int b  = m0 >> 10;
        const int node0 = (m0 & 1023) + hf * 64;
        __half* dh = htQ + ((long long)(b * NF + n0 + f) * NN) + node0;
#pragma unroll
        for (int i0 = 0; i0 < 64; i0 += 8) {
            uint4 hq;
            uint32_t* hw = (uint32_t*)&hq;
#pragma unroll
            for (int e = 0; e < 4; e++) {
                float x0 = ts[(hf * 64 + i0 + e * 2)     * 129 + f];
                float x1 = ts[(hf * 64 + i0 + e * 2 + 1) * 129 + f];
                hw[e] = packq(x0, x1);
            }
            *(uint4*)(dh + i0) = hq;
        }
    }
}

// ============ pure fp16 GEMM (GEMM2/GEMM4): both operands preformed =========
// A: fp16 [b][M][K], B: fp16 [b][N][K], C: fp32 [b][M][N]. EPI: 0 none, 1 ELU.
template <int EPI>
__global__ void __launch_bounds__(256, 2)
tc_gemmq(const __half* __restrict__ Aq, const __half* __restrict__ Bq,
         float* __restrict__ C, int N, int K,
         long long sA, long long sB, long long sC)
{
    extern __shared__ char smem[];
    constexpr int BUF = 16384;
    constexpr int OA = 0, OB = 8192;

    const int bz = blockIdx.z;
    Aq += (long long)bz * sA;
    Bq += (long long)bz * sB;
    C  += (long long)bz * sC;

    const int m0 = blockIdx.y * 128;
    const int n0 = blockIdx.x * 128;
    const int tid  = threadIdx.x;
    const int warp = tid >> 5, lane = tid & 31;
    const int mw = (warp >> 2) * 64;
    const int nw = (warp & 3) * 32;
    const uint32_t sb = smem_u32(smem);

    auto produce = [&](int c, int buf) {
        const int k0 = c << 5;
        const uint32_t dA = sb + buf * BUF + OA;
        const uint32_t dB = sb + buf * BUF + OB;
#pragma unroll
        for (int rep = 0; rep < 2; rep++) {
            int idx = tid + rep * 256;
            int row = idx >> 2, q = idx & 3;
            uint32_t so = sw64(row * 64 + q * 16);
            cpasync16(dA + so, Aq + (long long)(m0 + row) * K + k0 + q * 8);
            cpasync16(dB + so, Bq + (long long)(n0 + row) * K + k0 + q * 8);
        }
        CP_COMMIT();
    };

    float acc[4][4][4] = {};
    auto consume = [&](int buf) {
        const uint32_t aB = sb + buf * BUF + OA;
        const uint32_t bB = sb + buf * BUF + OB;
        const uint32_t aRow = (lane & 15);
        const uint32_t aKof = (lane >> 4) * 16;
        const uint32_t bRow = (lane & 7);
        const uint32_t bKof = ((lane >> 3) & 1) * 16;
#pragma unroll
        for (int ks = 0; ks < 2; ks++) {
            const uint32_t kb = ks * 32;
            unsigned ah[4][4], bh[4][2];
#pragma unroll
            for (int mt = 0; mt < 4; mt++) {
                uint32_t off = sw64((mw + mt * 16 + aRow) * 64 + kb + aKof);
                ldx4(ah[mt], aB + off);
            }
#pragma unroll
            for (int nt = 0; nt < 4; nt++) {
                uint32_t off = sw64((nw + nt * 8 + bRow) * 64 + kb + bKof);
                ldx2(bh[nt], bB + off);
            }
#pragma unroll
            for (int mt = 0; mt < 4; mt++)
#pragma unroll
                for (int nt = 0; nt < 4; nt++)
                    mma16816(acc[mt][nt], ah[mt], bh[nt]);
        }
    };

    const int nCh = K >> 5;
    produce(0, 0);
    CP_WAIT0();
    __syncthreads();
    int buf = 0;
    for (int c = 0; c < nCh; c++) {
        if (c + 1 < nCh) produce(c + 1, buf ^ 1);
        consume(buf);
        CP_WAIT0();
        __syncthreads();
        buf ^= 1;
    }

    const int r0 = lane >> 2;
    const int cc = (lane & 3) * 2;
#pragma unroll
    for (int mt = 0; mt < 4; mt++) {
#pragma unroll
        for (int nt = 0; nt < 4; nt++) {
            float* a4 = acc[mt][nt];
            if (EPI == 1) {
#pragma unroll
                for (int e = 0; e < 4; e++)
                    a4[e] = a4[e] > 0.f ? a4[e] : (__expf(a4[e]) - 1.f);
            }
            const int col = n0 + nw + nt * 8 + cc;
            const int row = m0 + mw + mt * 16 + r0;
            *(float2*)&C[(long long)row * N + col]       = make_float2(a4[0], a4[1]);
            *(float2*)&C[(long long)(row + 8) * N + col] = make_float2(a4[2], a4[3]);
        }
    }
}

// ============ attention generator: fp16 att (+ optional fp32) ================
// grid (NN/8, B_), 256 threads (warp per row). Stats computed inline per block.
template <int WRITE32>
__global__ void __launch_bounds__(256)
att_gen(const float* __restrict__ elP, const float* __restrict__ erP,
        __half* __restrict__ attq, float* __restrict__ att32)
{
    __shared__ float ser[NN];
    __shared__ float red[4][8];
    __shared__ float sstat[2];
    const int bz = blockIdx.y;
    const int tid = threadIdx.x;
    const int warp = tid >> 5, lane = tid & 31;

    float mnl = 1e30f, mxl = -1e30f, mnr = 1e30f, mxr = -1e30f;
    for (int i = tid; i < NN; i += 256) {
        float l = elP[bz * NN + i] + elP[TOT + bz * NN + i];
        float r = erP[bz * NN + i] + erP[TOT + bz * NN + i];
        ser[i] = r;
        mnl = fminf(mnl, l); mxl = fmaxf(mxl, l);
        mnr = fminf(mnr, r); mxr = fmaxf(mxr, r);
    }
#pragma unroll
    for (int o = 16; o; o >>= 1) {
        mnl = fminf(mnl, __shfl_xor_sync(0xFFFFFFFFu, mnl, o));
        mxl = fmaxf(mxl, __shfl_xor_sync(0xFFFFFFFFu, mxl, o));
        mnr = fminf(mnr, __shfl_xor_sync(0xFFFFFFFFu, mnr, o));
        mxr = fmaxf(mxr, __shfl_xor_sync(0xFFFFFFFFu, mxr, o));
    }
    if (lane == 0) { red[0][warp] = mnl; red[1][warp] = mxl; red[2][warp] = mnr; red[3][warp] = mxr; }
    __syncthreads();
    if (tid == 0) {
        float a0 = red[0][0], a1 = red[1][0], a2 = red[2][0], a3 = red[3][0];
#pragma unroll
        for (int i = 1; i < 8; i++) {
            a0 = fminf(a0, red[0][i]); a1 = fmaxf(a1, red[1][i]);
            a2 = fminf(a2, red[2][i]); a3 = fmaxf(a3, red[3][i]);
        }
        float lo = a0 + a2, hi = a1 + a3;
        float mn = lo >= 0.f ? lo : 0.01f * lo;
        float mx = hi >= 0.f ? hi : 0.01f * hi;
        sstat[0] = mn;
        sstat[1] = 30.f / (mx - mn);
    }
    __syncthreads();
    const float mn = sstat[0], kk = sstat[1];

    const int row = blockIdx.x * 8 + warp;
    const float elv = elP[bz * NN + row] + elP[TOT + bz * NN + row];
    __half* aq = attq + ((long long)bz * NN + row) * NN;
    float* a32 = WRITE32 ? (att32 + ((long long)bz * NN + row) * NN) : nullptr;

    for (int j0 = lane * 4; j0 < NN; j0 += 128) {
        float4 r4 = *(const float4*)&ser[j0];
        float s0, s1, s2, s3;
        {
            float x = elv + r4.x; float lr = x >= 0.f ? x : 0.01f * x;
            s0 = fast_sigmoid_z(fmaf(lr - mn, kk, -20.f));
        }
        {
            float x = elv + r4.y; float lr = x >= 0.f ? x : 0.01f * x;
            s1 = fast_sigmoid_z(fmaf(lr - mn, kk, -20.f));
        }
        {
            float x = elv + r4.z; float lr = x >= 0.f ? x : 0.01f * x;
            s2 = fast_sigmoid_z(fmaf(lr - mn, kk, -20.f));
        }
        {
            float x = elv + r4.w; float lr = x >= 0.f ? x : 0.01f * x;
            s3 = fast_sigmoid_z(fmaf(lr - mn, kk, -20.f));
        }
        uint2 hv;
        hv.x = packq(s0, s1);
        hv.y = packq(s2, s3);
        *(uint2*)(aq + j0) = hv;
        if (WRITE32) *(float4*)(a32 + j0) = make_float4(s0, s1, s2, s3);
    }
}

// ---------------- transpose + fp16 exact split (weights) --------------------
__global__ void prepT(const float* __restrict__ src, __half* __restrict__ dhi,
                      __half* __restrict__ dlo, int R, int Cc)
{
    __shared__ float t[32][33];
    const int c0 = blockIdx.x * 32;
    const int r0 = blockIdx.y * 32;
    const int tx = threadIdx.x, ty = threadIdx.y;
#pragma unroll
    for (int i = ty; i < 32; i += 8)
        t[i][tx] = src[(long long)(r0 + i) * Cc + c0 + tx];
    __syncthreads();
#pragma unroll
    for (int i = ty; i < 32; i += 8) {
        float v = t[tx][i];
        __half h = __float2half_rn(v);
        float rr = v - __half2float(h);
        dhi[(long long)(c0 + i) * R + r0 + tx] = h;
        dlo[(long long)(c0 + i) * R + r0 + tx] = __float2half_rn(rr);
    }
}

// ---------------- gv = g2 @ Wg ----------------------------------------------
__global__ void gv_kernel(const float* __restrict__ g2, const float* __restrict__ Wg,
                          float* __restrict__ gv)
{
    const int row  = (blockIdx.x * blockDim.x + threadIdx.x) >> 5;
    const int lane = threadIdx.x & 31;
    const float* gp = g2 + (long long)row * H2_;
    float s = fmaf(gp[lane], Wg[lane], gp[lane + 32] * Wg[lane + 32]);
    s = fmaf(gp[lane + 64], Wg[lane + 64], s);
    s = fmaf(gp[lane + 96], Wg[lane + 96], s);
#pragma unroll
    for (int o = 16; o; o >>= 1) s += __shfl_xor_sync(0xFFFFFFFFu, s, o);
    if (lane == 0) gv[row] = s;
}

// ---------------- out = leaky(fc2 @ gv + bg) ----------------------------------
__global__ void z_kernel(const float* __restrict__ fc2, const float* __restrict__ gv,
                         const float* __restrict__ bg, float* __restrict__ out)
{
    const int row  = (blockIdx.x * blockDim.x + threadIdx.x) >> 5;
    const int lane = threadIdx.x & 31;
    const int b = row >> 10;
    const float* fr = fc2 + (long long)row * NN;
    const float* gr = gv + b * NN;
    float s = 0.f;
#pragma unroll
    for (int j = lane * 4; j < NN; j += 128) {
        float4 f = *(const float4*)&fr[j];
        float4 g = *(const float4*)&gr[j];
        s = fmaf(f.x, g.x, s); s = fmaf(f.y, g.y, s);
        s = fmaf(f.z, g.z, s); s = fmaf(f.w, g.w, s);
    }
#pragma unroll
    for (int o = 16; o; o >>= 1) s += __shfl_xor_sync(0xFFFFFFFFu, s, o);
    if (lane == 0) {
        float z = s + bg[0];
        out[row] = z >= 0.f ? z : 0.01f * z;
    }
}

// ---------------------------------------------------------------------------
template <typename T>
static T* sym_p(const void* s)
{
    void* p = nullptr;
    cudaGetSymbolAddress(&p, s);
    return (T*)p;
}

extern "C" void kernel_launch(void* const* d_in, const int* in_sizes, int n_in,
                              void* d_out, int out_size)
{
    const float* x  = (const float*)d_in[0];
    const float* W1 = (const float*)d_in[2];
    const float* a1 = (const float*)d_in[3];
    const float* W2 = (const float*)d_in[4];
    const float* a2 = (const float*)d_in[5];
    const float* Wg = (const float*)d_in[6];
    const float* bg = (const float*)d_in[7];

    float* out = (float*)d_out;
    float* fc2 = out + (long long)B_ * NN;
    float* g2  = fc2 + (long long)B_ * NN * NN;

    float* g1   = sym_p<float>(d_g1);
    float* elP  = sym_p<float>(d_elP);
    float* erP  = sym_p<float>(d_erP);
    float* gv   = sym_p<float>(d_gv);
    __half* att1q = sym_p<__half>(d_att1q);
    __half* att2q = sym_p<__half>(d_att2q);
    __half* ht1  = sym_p<__half>(d_ht1);
    __half* ht2  = sym_p<__half>(d_ht2);
    __half* wt1h = sym_p<__half>(d_wt1_hi);
    __half* wt1l = sym_p<__half>(d_wt1_lo);
    __half* wt2h = sym_p<__half>(d_wt2_hi);
    __half* wt2l = sym_p<__half>(d_wt2_lo);

    const int SMBQ   = 2 * 16384;           // 32 KB (pure fp16 GEMM)
    const int SMB_TR = 128 * 129 * 4 + 512; // 66.5 KB (3-term + staging)
    cudaFuncSetAttribute(tc_gemm3<1>, cudaFuncAttributeMaxDynamicSharedMemorySize, SMB_TR);
    cudaFuncSetAttribute(tc_gemm3<2>, cudaFuncAttributeMaxDynamicSharedMemorySize, SMB_TR);
    cudaFuncSetAttribute(tc_gemmq<1>, cudaFuncAttributeMaxDynamicSharedMemorySize, SMBQ);
    cudaFuncSetAttribute(tc_gemmq<0>, cudaFuncAttributeMaxDynamicSharedMemorySize, SMBQ);

    const int rowsTot = B_ * NN;              // 32768
    const dim3 tp(32, 8);

    // ===== weight preps =====
    prepT<<<dim3(H1_ / 32, FIN / 32, 1), tp>>>(W1, wt1h, wt1l, FIN, H1_);
    prepT<<<dim3(H2_ / 32, H1_ / 32, 1), tp>>>(W2, wt2h, wt2l, H1_, H2_);

    // ===== Layer 1 =====
    // h1 = x @ W1 (exact); writes ht1 (transposed fp16) + el/er parts
    tc_gemm3<1><<<dim3(H1_ / 128, rowsTot / 128, 1), 256, SMB_TR>>>(
        x, wt1h, wt1l, FIN, a1, H1_, ht1, elP, erP);
    // att1 (fp16) from el/er; stats inline
    att_gen<0><<<dim3(NN / 8, B_), 256>>>(elP, erP, att1q, nullptr);
    // g1 = elu(att1 @ h1)
    tc_gemmq<1><<<dim3(H1_ / 128, NN / 128, B_), 256, SMBQ>>>(
        att1q, ht1, g1, H1_, NN,
        (long long)NN * NN, (long long)H1_ * NN, (long long)NN * H1_);

    // ===== Layer 2 =====
    // h2 = g1 @ W2 (exact); writes ht2 + el/er (part1 zeroed)
    tc_gemm3<2><<<dim3(H2_ / 128, rowsTot / 128, 1), 256, SMB_TR>>>(
        g1, wt2h, wt2l, H1_, a2, H2_, ht2, elP, erP);
    // att2: writes fp16 operand AND fp32 fc2 output
    att_gen<1><<<dim3(NN / 8, B_), 256>>>(elP, erP, att2q, fc2);
    // g2 = att2 @ h2
    tc_gemmq<0><<<dim3(H2_ / 128, NN / 128, B_), 256, SMBQ>>>(
        att2q, ht2, g2, H2_, NN,
        (long long)NN * NN, (long long)H2_ * NN, (long long)NN * H2_);

    // ===== Head: out = leaky(fc2 @ (g2 @ Wg) + bg) =====
    gv_kernel<<<rowsTot / 8, 256>>>(g2, Wg, gv);
    z_kernel<<<rowsTot / 8, 256>>>(fc2, gv, bg, out);
}

// round 16
// speedup vs baseline: 1.8498x; 1.0718x over previous
#include <cuda_runtime.h>
#include <cuda_fp16.h>
#include <math.h>
#include <stdint.h>

#define B_   32
#define NN   1024
#define FIN  512
#define H1_  256
#define H2_  128
#define TOT  32768

// ---------------- scratch (device globals; no allocation allowed) ----------
__device__ float d_g1[B_ * NN * H1_];
__device__ float d_elP[2 * TOT];
__device__ float d_erP[2 * TOT];
__device__ float d_gv[B_ * NN];
__device__ __half d_att1q[(long long)B_ * NN * NN];
__device__ __half d_att2q[(long long)B_ * NN * NN];
__device__ __half d_ht1[B_ * H1_ * NN];
__device__ __half d_ht2[B_ * H2_ * NN];
__device__ __half d_wt1_hi[H1_ * FIN];    // W1 exact split
__device__ __half d_wt1_lo[H1_ * FIN];
__device__ __half d_wt2_hi[H2_ * H1_];    // W2 exact split
__device__ __half d_wt2_lo[H2_ * H1_];

__device__ __forceinline__ uint32_t smem_u32(const void* p) {
    return (uint32_t)__cvta_generic_to_shared(p);
}
__device__ __forceinline__ uint32_t sw64(uint32_t off) {
    return off ^ ((off >> 3) & 0x30);
}
__device__ __forceinline__ uint32_t sw128(uint32_t off) {
    return off ^ ((off >> 3) & 0x70);
}
__device__ __forceinline__ float fast_sigmoid_z(float z) {
    float t;
    asm("tanh.approx.f32 %0, %1;" : "=f"(t) : "f"(0.5f * z));
    return fmaf(0.5f, t, 0.5f);
}
__device__ __forceinline__ void ldx4(unsigned* r, uint32_t addr) {
    asm volatile("ldmatrix.sync.aligned.m8n8.x4.shared.b16 {%0,%1,%2,%3}, [%4];"
                 : "=r"(r[0]), "=r"(r[1]), "=r"(r[2]), "=r"(r[3]) : "r"(addr));
}
__device__ __forceinline__ void ldx2(unsigned* r, uint32_t addr) {
    asm volatile("ldmatrix.sync.aligned.m8n8.x2.shared.b16 {%0,%1}, [%2];"
                 : "=r"(r[0]), "=r"(r[1]) : "r"(addr));
}
__device__ __forceinline__ void mma16816(float* c, const unsigned* a, const unsigned* b) {
    asm volatile(
        "mma.sync.aligned.m16n8k16.row.col.f32.f16.f16.f32 "
        "{%0,%1,%2,%3}, {%4,%5,%6,%7}, {%8,%9}, {%0,%1,%2,%3};"
        : "+f"(c[0]), "+f"(c[1]), "+f"(c[2]), "+f"(c[3])
        : "r"(a[0]), "r"(a[1]), "r"(a[2]), "r"(a[3]), "r"(b[0]), "r"(b[1]));
}
__device__ __forceinline__ void cpasync16(uint32_t saddr, const void* gptr) {
    asm volatile("cp.async.cg.shared.global [%0], [%1], 16;"
                 :: "r"(saddr), "l"(gptr) : "memory");
}
#define CP_COMMIT() asm volatile("cp.async.commit_group;" ::: "memory")
#define CP_WAIT0()  asm volatile("cp.async.wait_group 0;" ::: "memory")

__device__ __forceinline__ uint32_t packsplit(float x0, float x1, uint32_t& lo) {
    __half h0 = __float2half_rn(x0), h1 = __float2half_rn(x1);
    float r0 = x0 - __half2float(h0);
    float r1 = x1 - __half2float(h1);
    __half l0 = __float2half_rn(r0), l1 = __float2half_rn(r1);
    lo = (uint32_t)__half_as_ushort(l0) | ((uint32_t)__half_as_ushort(l1) << 16);
    return (uint32_t)__half_as_ushort(h0) | ((uint32_t)__half_as_ushort(h1) << 16);
}
__device__ __forceinline__ uint32_t packq(float x0, float x1) {
    return (uint32_t)__half_as_ushort(__float2half_rn(x0)) |
           ((uint32_t)__half_as_ushort(__float2half_rn(x1)) << 16);
}

// ============ 3-term exact GEMM with transposing epilogue (GEMM1/GEMM3) ======
// A: [M,K] fp32 exact hi/lo split; B: fp16 exact hi/lo split.
// Epilogue writes transposed fp16 plane htQ [b][feat][node] + el/er partials.
// TR 1: part = n0>>7 (two n-CTAs). TR 2: part0 = value, part1 = 0.
template <int TR>
__global__ void __launch_bounds__(256, 2)
tc_gemm3(const float* __restrict__ A,
         const __half* __restrict__ Bhi, const __half* __restrict__ Blo,
         int K,
         const float* __restrict__ av, int NF,
         __half* __restrict__ htQ,
         float* __restrict__ elO, float* __restrict__ erO)
{
    extern __shared__ char smem[];
    constexpr int BUF = 32768;
    constexpr int OAH = 0, OAL = 8192, OBH = 16384, OBL = 24576;

    const int m0 = blockIdx.y * 128;
    const int n0 = blockIdx.x * 128;
    const int tid  = threadIdx.x;
    const int warp = tid >> 5, lane = tid & 31;
    const int mw = (warp >> 2) * 64;
    const int nw = (warp & 3) * 32;
    const uint32_t sb = smem_u32(smem);

    const int ar = tid >> 1;
    const int ac = (tid & 1) * 16;
    float va[16];

    auto produce_load = [&](int c) {
        const int k0 = c << 5;
        const float4* Sp = (const float4*)(A + (long long)(m0 + ar) * K + k0 + ac);
#pragma unroll
        for (int q = 0; q < 4; q++) {
            float4 f = Sp[q];
            va[q * 4 + 0] = f.x; va[q * 4 + 1] = f.y;
            va[q * 4 + 2] = f.z; va[q * 4 + 3] = f.w;
        }
    };
    auto produce_B = [&](int c, int buf) {
        const int k0 = c << 5;
        const uint32_t dH = sb + buf * BUF + OBH;
        const uint32_t dL = sb + buf * BUF + OBL;
#pragma unroll
        for (int rep = 0; rep < 2; rep++) {
            int idx = tid + rep * 256;
            int row = idx >> 2, q = idx & 3;
            uint32_t so = sw64(row * 64 + q * 16);
            cpasync16(dH + so, Bhi + (long long)(n0 + row) * K + k0 + q * 8);
            cpasync16(dL + so, Blo + (long long)(n0 + row) * K + k0 + q * 8);
        }
        CP_COMMIT();
    };
    auto produce_store = [&](int buf) {
        char* base = smem + buf * BUF;
#pragma unroll
        for (int g = 0; g < 2; g++) {
            uint4 hq, lq;
            uint32_t* hw = (uint32_t*)&hq;
            uint32_t* lw = (uint32_t*)&lq;
#pragma unroll
            for (int e = 0; e < 4; e++)
                hw[e] = packsplit(va[g * 8 + e * 2], va[g * 8 + e * 2 + 1], lw[e]);
            uint32_t so = sw64(ar * 64 + ac * 2 + g * 16);
            *(uint4*)(base + OAH + so) = hq;
            *(uint4*)(base + OAL + so) = lq;
        }
    };

    float acc[4][4][4] = {};
    auto consume = [&](int buf) {
        const uint32_t aH = sb + buf * BUF + OAH;
        const uint32_t aL = sb + buf * BUF + OAL;
        const uint32_t bB = sb + buf * BUF + OBH;
        const uint32_t bLo = sb + buf * BUF + OBL;
        const uint32_t aRow = (lane & 15);
        const uint32_t aKof = (lane >> 4) * 16;
        const uint32_t bRow = (lane & 7);
        const uint32_t bKof = ((lane >> 3) & 1) * 16;
#pragma unroll
        for (int ks = 0; ks < 2; ks++) {
            const uint32_t kb = ks * 32;
            unsigned ah[4][4], al[4][4], bh[4][2], bl[4][2];
#pragma unroll
            for (int mt = 0; mt < 4; mt++) {
                uint32_t off = sw64((mw + mt * 16 + aRow) * 64 + kb + aKof);
                ldx4(ah[mt], aH + off);
                ldx4(al[mt], aL + off);
            }
#pragma unroll
            for (int nt = 0; nt < 4; nt++) {
                uint32_t off = sw64((nw + nt * 8 + bRow) * 64 + kb + bKof);
                ldx2(bh[nt], bB + off);
                ldx2(bl[nt], bLo + off);
            }
#pragma unroll
            for (int mt = 0; mt < 4; mt++)
#pragma unroll
                for (int nt = 0; nt < 4; nt++)
                    mma16816(acc[mt][nt], ah[mt], bh[nt]);
#pragma unroll
            for (int mt = 0; mt < 4; mt++)
#pragma unroll
                for (int nt = 0; nt < 4; nt++)
                    mma16816(acc[mt][nt], al[mt], bh[nt]);
#pragma unroll
            for (int mt = 0; mt < 4; mt++)
#pragma unroll
                for (int nt = 0; nt < 4; nt++)
                    mma16816(acc[mt][nt], ah[mt], bl[nt]);
        }
    };

    const int nCh = K >> 5;
    produce_load(0);
    produce_B(0, 0);
    produce_store(0);
    CP_WAIT0();
    __syncthreads();
    int buf = 0;
    for (int c = 0; c < nCh; c++) {
        const bool more = (c + 1 < nCh);
        if (more) {
            produce_load(c + 1);
            produce_B(c + 1, buf ^ 1);
        }
        consume(buf);
        if (more) produce_store(buf ^ 1);
        CP_WAIT0();
        __syncthreads();
        buf ^= 1;
    }

    // ---- transposing epilogue ----
    const int r0 = lane >> 2;
    const int cc = (lane & 3) * 2;
    __syncthreads();
    float* ts = (float*)smem;
#pragma unroll
    for (int mt = 0; mt < 4; mt++) {
#pragma unroll
        for (int nt = 0; nt < 4; nt++) {
            float* a4 = acc[mt][nt];
            const int row = mw + mt * 16 + r0;
            const int col = nw + nt * 8 + cc;
            ts[row * 129 + col]           = a4[0];
            ts[row * 129 + col + 1]       = a4[1];
            ts[(row + 8) * 129 + col]     = a4[2];
            ts[(row + 8) * 129 + col + 1] = a4[3];
        }
    }
    __syncthreads();
    {
        const int row = tid >> 1;
        const int hf  = tid & 1;
        const float* tr = ts + row * 129 + hf * 64;
        const float* aLp = av + n0 + hf * 64;
        const float* aRp = av + NF + n0 + hf * 64;
        float sl = 0.f, sr = 0.f;
#pragma unroll
        for (int f = 0; f < 64; f++) {
            float v = tr[f];
            sl = fmaf(v, aLp[f], sl);
            sr = fmaf(v, aRp[f], sr);
        }
        sl += __shfl_xor_sync(0xFFFFFFFFu, sl, 1);
        sr += __shfl_xor_sync(0xFFFFFFFFu, sr, 1);
        if (hf == 0) {
            const int grow = m0 + row;
            if (TR == 1) {
                const int part = n0 >> 7;
                elO[part * TOT + grow] = sl;
                erO[part * TOT + grow] = sr;
            } else {
                elO[grow] = sl; elO[TOT + grow] = 0.f;
                erO[grow] = sr; erO[TOT + grow] = 0.f;
            }
        }
    }
    {
        const int f  = tid >> 1;
        const int hf = tid & 1;
        const int b  = m0 >> 10;
        const int node0 = (m0 & 1023) + hf * 64;
        __half* dh = htQ + ((long long)(b * NF + n0 + f) * NN) + node0;
#pragma unroll
        for (int i0 = 0; i0 < 64; i0 += 8) {
            uint4 hq;
            uint32_t* hw = (uint32_t*)&hq;
#pragma unroll
            for (int e = 0; e < 4; e++) {
                float x0 = ts[(hf * 64 + i0 + e * 2)     * 129 + f];
                float x1 = ts[(hf * 64 + i0 + e * 2 + 1) * 129 + f];
                hw[e] = packq(x0, x1);
            }
            *(uint4*)(dh + i0) = hq;
        }
    }
}

// ============ pure fp16 GEMM (GEMM2/GEMM4), BK=64, SW128 ====================
template <int EPI>
__global__ void __launch_bounds__(256, 2)
tc_gemmq(const __half* __restrict__ Aq, const __half* __restrict__ Bq,
         float* __restrict__ C, int N, int K,
         long long sA, long long sB, long long sC)
{
    extern __shared__ char smem[];
    constexpr int BUF = 32768;           // A 16K | B 16K per buffer
    constexpr int OA = 0, OB = 16384;

    const int bz = blockIdx.z;
    Aq += (long long)bz * sA;
    Bq += (long long)bz * sB;
    C  += (long long)bz * sC;

    const int m0 = blockIdx.y * 128;
    const int n0 = blockIdx.x * 128;
    const int tid  = threadIdx.x;
    const int warp = tid >> 5, lane = tid & 31;
    const int mw = (warp >> 2) * 64;
    const int nw = (warp & 3) * 32;
    const uint32_t sb = smem_u32(smem);

    auto produce = [&](int c, int buf) {
        const int k0 = c << 6;
        const uint32_t dA = sb + buf * BUF + OA;
        const uint32_t dB = sb + buf * BUF + OB;
#pragma unroll
        for (int rep = 0; rep < 4; rep++) {
            int idx = tid + rep * 256;         // 0..1023 granules per plane
            int row = idx >> 3, q = idx & 7;
            uint32_t so = sw128(row * 128 + q * 16);
            cpasync16(dA + so, Aq + (long long)(m0 + row) * K + k0 + q * 8);
            cpasync16(dB + so, Bq + (long long)(n0 + row) * K + k0 + q * 8);
        }
        CP_COMMIT();
    };

    float acc[4][4][4] = {};
    auto consume = [&](int buf) {
        const uint32_t aB = sb + buf * BUF + OA;
        const uint32_t bB = sb + buf * BUF + OB;
        const uint32_t aRow = (lane & 15);
        const uint32_t aKof = (lane >> 4) * 16;
        const uint32_t bRow = (lane & 7);
        const uint32_t bKof = ((lane >> 3) & 1) * 16;
#pragma unroll
        for (int ks = 0; ks < 4; ks++) {
            const uint32_t kb = ks * 32;
            unsigned ah[4][4], bh[4][2];
#pragma unroll
            for (int mt = 0; mt < 4; mt++) {
                uint32_t off = sw128((mw + mt * 16 + aRow) * 128 + kb + aKof);
                ldx4(ah[mt], aB + off);
            }
#pragma unroll
            for (int nt = 0; nt < 4; nt++) {
                uint32_t off = sw128((nw + nt * 8 + bRow) * 128 + kb + bKof);
                ldx2(bh[nt], bB + off);
            }
#pragma unroll
            for (int mt = 0; mt < 4; mt++)
#pragma unroll
                for (int nt = 0; nt < 4; nt++)
                    mma16816(acc[mt][nt], ah[mt], bh[nt]);
        }
    };

    const int nCh = K >> 6;
    produce(0, 0);
    CP_WAIT0();
    __syncthreads();
    int buf = 0;
    for (int c = 0; c < nCh; c++) {
        if (c + 1 < nCh) produce(c + 1, buf ^ 1);
        consume(buf);
        CP_WAIT0();
        __syncthreads();
        buf ^= 1;
    }

    const int r0 = lane >> 2;
    const int cc = (lane & 3) * 2;
#pragma unroll
    for (int mt = 0; mt < 4; mt++) {
#pragma unroll
        for (int nt = 0; nt < 4; nt++) {
            float* a4 = acc[mt][nt];
            if (EPI == 1) {
#pragma unroll
                for (int e = 0; e < 4; e++)
                    a4[e] = a4[e] > 0.f ? a4[e] : (__expf(a4[e]) - 1.f);
            }
            const int col = n0 + nw + nt * 8 + cc;
            const int row = m0 + mw + mt * 16 + r0;
            *(float2*)&C[(long long)row * N + col]       = make_float2(a4[0], a4[1]);
            *(float2*)&C[(long long)(row + 8) * N + col] = make_float2(a4[2], a4[3]);
        }
    }
}

// ============ attention generator ===========================================
template <int WRITE32>
__global__ void __launch_bounds__(256)
att_gen(const float* __restrict__ elP, const float* __restrict__ erP,
        __half* __restrict__ attq, float* __restrict__ att32)
{
    __shared__ float ser[NN];
    __shared__ float red[4][8];
    __shared__ float sstat[2];
    const int bz = blockIdx.y;
    const int tid = threadIdx.x;
    const int warp = tid >> 5, lane = tid & 31;

    float mnl = 1e30f, mxl = -1e30f, mnr = 1e30f, mxr = -1e30f;
    for (int i = tid; i < NN; i += 256) {
        float l = elP[bz * NN + i] + elP[TOT + bz * NN + i];
        float r = erP[bz * NN + i] + erP[TOT + bz * NN + i];
        ser[i] = r;
        mnl = fminf(mnl, l); mxl = fmaxf(mxl, l);
        mnr = fminf(mnr, r); mxr = fmaxf(mxr, r);
    }
#pragma unroll
    for (int o = 16; o; o >>= 1) {
        mnl = fminf(mnl, __shfl_xor_sync(0xFFFFFFFFu, mnl, o));
        mxl = fmaxf(mxl, __shfl_xor_sync(0xFFFFFFFFu, mxl, o));
        mnr = fminf(mnr, __shfl_xor_sync(0xFFFFFFFFu, mnr, o));
        mxr = fmaxf(mxr, __shfl_xor_sync(0xFFFFFFFFu, mxr, o));
    }
    if (lane == 0) { red[0][warp] = mnl; red[1][warp] = mxl; red[2][warp] = mnr; red[3][warp] = mxr; }
    __syncthreads();
    if (tid == 0) {
        float a0 = red[0][0], a1 = red[1][0], a2 = red[2][0], a3 = red[3][0];
#pragma unroll
        for (int i = 1; i < 8; i++) {
            a0 = fminf(a0, red[0][i]); a1 = fmaxf(a1, red[1][i]);
            a2 = fminf(a2, red[2][i]); a3 = fmaxf(a3, red[3][i]);
        }
        float lo = a0 + a2, hi = a1 + a3;
        float mn = lo >= 0.f ? lo : 0.01f * lo;
        float mx = hi >= 0.f ? hi : 0.01f * hi;
        sstat[0] = mn;
        sstat[1] = 30.f / (mx - mn);
    }
    __syncthreads();
    const float mn = sstat[0], kk = sstat[1];

    const int row = blockIdx.x * 8 + warp;
    const float elv = elP[bz * NN + row] + elP[TOT + bz * NN + row];
    __half* aq = attq + ((long long)bz * NN + row) * NN;
    float* a32 = WRITE32 ? (att32 + ((long long)bz * NN + row) * NN) : nullptr;

    for (int j0 = lane * 4; j0 < NN; j0 += 128) {
        float4 r4 = *(const float4*)&ser[j0];
        float s0, s1, s2, s3;
        {
            float x = elv + r4.x; float lr = x >= 0.f ? x : 0.01f * x;
            s0 = fast_sigmoid_z(fmaf(lr - mn, kk, -20.f));
        }
        {
            float x = elv + r4.y; float lr = x >= 0.f ? x : 0.01f * x;
            s1 = fast_sigmoid_z(fmaf(lr - mn, kk, -20.f));
        }
        {
            float x = elv + r4.z; float lr = x >= 0.f ? x : 0.01f * x;
            s2 = fast_sigmoid_z(fmaf(lr - mn, kk, -20.f));
        }
        {
            float x = elv + r4.w; float lr = x >= 0.f ? x : 0.01f * x;
            s3 = fast_sigmoid_z(fmaf(lr - mn, kk, -20.f));
        }
        uint2 hv;
        hv.x = packq(s0, s1);
        hv.y = packq(s2, s3);
        *(uint2*)(aq + j0) = hv;
        if (WRITE32) *(float4*)(a32 + j0) = make_float4(s0, s1, s2, s3);
    }
}

// ---------------- transpose + fp16 exact split (weights) --------------------
__global__ void prepT(const float* __restrict__ src, __half* __restrict__ dhi,
                      __half* __restrict__ dlo, int R, int Cc)
{
    __shared__ float t[32][33];
    const int c0 = blockIdx.x * 32;
    const int r0 = blockIdx.y * 32;
    const int tx = threadIdx.x, ty = threadIdx.y;
#pragma unroll
    for (int i = ty; i < 32; i += 8)
        t[i][tx] = src[(long long)(r0 + i) * Cc + c0 + tx];
    __syncthreads();
#pragma unroll
    for (int i = ty; i < 32; i += 8) {
        float v = t[tx][i];
        __half h = __float2half_rn(v);
        float rr = v - __half2float(h);
        dhi[(long long)(c0 + i) * R + r0 + tx] = h;
        dlo[(long long)(c0 + i) * R + r0 + tx] = __float2half_rn(rr);
    }
}

// ---------------- gv = g2 @ Wg ----------------------------------------------
__global__ void gv_kernel(const float* __restrict__ g2, const float* __restrict__ Wg,
                          float* __restrict__ gv)
{
    const int row  = (blockIdx.x * blockDim.x + threadIdx.x) >> 5;
    const int lane = threadIdx.x & 31;
    const float* gp = g2 + (long long)row * H2_;
    float s = fmaf(gp[lane], Wg[lane], gp[lane + 32] * Wg[lane + 32]);
    s = fmaf(gp[lane + 64], Wg[lane + 64], s);
    s = fmaf(gp[lane + 96], Wg[lane + 96], s);
#pragma unroll
    for (int o = 16; o; o >>= 1) s += __shfl_xor_sync(0xFFFFFFFFu, s, o);
    if (lane == 0) gv[row] = s;
}

// ---------------- out = leaky(att2q @ gv + bg), fp16 matrix ------------------
__global__ void z_kernel(const __half* __restrict__ fc2h, const float* __restrict__ gv,
                         const float* __restrict__ bg, float* __restrict__ out)
{
    const int row  = (blockIdx.x * blockDim.x + threadIdx.x) >> 5;
    const int lane = threadIdx.x & 31;
    const int b = row >> 10;
    const __half* fr = fc2h + (long long)row * NN;
    const float* gr = gv + b * NN;
    float s = 0.f;
#pragma unroll
    for (int j = lane * 4; j < NN; j += 128) {
        uint2 hv = *(const uint2*)(fr + j);
        __half2 f01 = *(__half2*)&hv.x;
        __half2 f23 = *(__half2*)&hv.y;
        float4 g = *(const float4*)&gr[j];
        s = fmaf(__low2float(f01),  g.x, s);
        s = fmaf(__high2float(f01), g.y, s);
        s = fmaf(__low2float(f23),  g.z, s);
        s = fmaf(__high2float(f23), g.w, s);
    }
#pragma unroll
    for (int o = 16; o; o >>= 1) s += __shfl_xor_sync(0xFFFFFFFFu, s, o);
    if (lane == 0) {
        float z = s + bg[0];
        out[row] = z >= 0.f ? z : 0.01f * z;
    }
}

// ---------------------------------------------------------------------------
template <typename T>
static T* sym_p(const void* s)
{
    void* p = nullptr;
    cudaGetSymbolAddress(&p, s);
    return (T*)p;
}

extern "C" void kernel_launch(void* const* d_in, const int* in_sizes, int n_in,
                              void* d_out, int out_size)
{
    const float* x  = (const float*)d_in[0];
    const float* W1 = (const float*)d_in[2];
    const float* a1 = (const float*)d_in[3];
    const float* W2 = (const float*)d_in[4];
    const float* a2 = (const float*)d_in[5];
    const float* Wg = (const float*)d_in[6];
    const float* bg = (const float*)d_in[7];

    float* out = (float*)d_out;
    float* fc2 = out + (long long)B_ * NN;
    float* g2  = fc2 + (long long)B_ * NN * NN;

    float* g1   = sym_p<float>(d_g1);
    float* elP  = sym_p<float>(d_elP);
    float* erP  = sym_p<float>(d_erP);
    float* gv   = sym_p<float>(d_gv);
    __half* att1q = sym_p<__half>(d_att1q);
    __half* att2q = sym_p<__half>(d_att2q);
    __half* ht1  = sym_p<__half>(d_ht1);
    __half* ht2  = sym_p<__half>(d_ht2);
    __half* wt1h = sym_p<__half>(d_wt1_hi);
    __half* wt1l = sym_p<__half>(d_wt1_lo);
    __half* wt2h = sym_p<__half>(d_wt2_hi);
    __half* wt2l = sym_p<__half>(d_wt2_lo);

    const int SMBQ   = 2 * 32768;           // 64 KB (pure fp16 GEMM, BK=64)
    const int SMB_TR = 128 * 129 * 4 + 512; // 66.5 KB
    cudaFuncSetAttribute(tc_gemm3<1>, cudaFuncAttributeMaxDynamicSharedMemorySize, SMB_TR);
    cudaFuncSetAttribute(tc_gemm3<2>, cudaFuncAttributeMaxDynamicSharedMemorySize, SMB_TR);
    cudaFuncSetAttribute(tc_gemmq<1>, cudaFuncAttributeMaxDynamicSharedMemorySize, SMBQ);
    cudaFuncSetAttribute(tc_gemmq<0>, cudaFuncAttributeMaxDynamicSharedMemorySize, SMBQ);

    const int rowsTot = B_ * NN;              // 32768
    const dim3 tp(32, 8);

    // ===== weight preps (exact hi/lo split) =====
    prepT<<<dim3(H1_ / 32, FIN / 32, 1), tp>>>(W1, wt1h, wt1l, FIN, H1_);
    prepT<<<dim3(H2_ / 32, H1_ / 32, 1), tp>>>(W2, wt2h, wt2l, H1_, H2_);

    // ===== Layer 1 =====
    // h1 = x @ W1 (3-term exact); writes ht1 (transposed fp16) + el/er parts
    tc_gemm3<1><<<dim3(H1_ / 128, rowsTot / 128, 1), 256, SMB_TR>>>(
        x, wt1h, wt1l, FIN, a1, H1_, ht1, elP, erP);
    att_gen<0><<<dim3(NN / 8, B_), 256>>>(elP, erP, att1q, nullptr);
    // g1 = elu(att1 @ h1)
    tc_gemmq<1><<<dim3(H1_ / 128, NN / 128, B_), 256, SMBQ>>>(
        att1q, ht1, g1, H1_, NN,
        (long long)NN * NN, (long long)H1_ * NN, (long long)NN * H1_);

    // ===== Layer 2 =====
    // h2 = g1 @ W2 (3-term exact); writes ht2 + el/er (part1 zeroed)
    tc_gemm3<2><<<dim3(H2_ / 128, rowsTot / 128, 1), 256, SMB_TR>>>(
        g1, wt2h, wt2l, H1_, a2, H2_, ht2, elP, erP);
    // att2: fp16 operand + fp32 fc2 output
    att_gen<1><<<dim3(NN / 8, B_), 256>>>(elP, erP, att2q, fc2);
    // g2 = att2 @ h2
    tc_gemmq<0><<<dim3(H2_ / 128, NN / 128, B_), 256, SMBQ>>>(
        att2q, ht2, g2, H2_, NN,
        (long long)NN * NN, (long long)H2_ * NN, (long long)NN * H2_);

    // ===== Head: out = leaky(fc2 @ (g2 @ Wg) + bg), fc2 via fp16 att2q =====
    gv_kernel<<<rowsTot / 8, 256>>>(g2, Wg, gv);
    z_kernel<<<rowsTot / 8, 256>>>(att2q, gv, bg, out);
}

// round 17
// speedup vs baseline: 1.8799x; 1.0163x over previous
#include <cuda_runtime.h>
#include <cuda_fp16.h>
#include <math.h>
#include <stdint.h>

#define B_   32
#define NN   1024
#define FIN  512
#define H1_  256
#define H2_  128
#define TOT  32768

// ---------------- scratch (device globals; no allocation allowed) ----------
__device__ float d_g1[B_ * NN * H1_];
__device__ float d_el[TOT];
__device__ float d_er[TOT];
__device__ float d_gv[B_ * NN];
__device__ float d_w1a[2 * FIN];
__device__ float d_w2a[2 * H1_];
__device__ __half d_att1q[(long long)B_ * NN * NN];
__device__ __half d_att2q[(long long)B_ * NN * NN];
__device__ __half d_ht1[B_ * H1_ * NN];
__device__ __half d_ht2[B_ * H2_ * NN];
__device__ __half d_wt1q[H1_ * FIN];      // W1 quantized transposed plane
__device__ __half d_wt2q[H2_ * H1_];      // W2 quantized transposed plane

__device__ __forceinline__ uint32_t smem_u32(const void* p) {
    return (uint32_t)__cvta_generic_to_shared(p);
}
__device__ __forceinline__ uint32_t sw64(uint32_t off) {
    return off ^ ((off >> 3) & 0x30);
}
__device__ __forceinline__ uint32_t sw128(uint32_t off) {
    return off ^ ((off >> 3) & 0x70);
}
__device__ __forceinline__ float fast_sigmoid_z(float z) {
    float t;
    asm("tanh.approx.f32 %0, %1;" : "=f"(t) : "f"(0.5f * z));
    return fmaf(0.5f, t, 0.5f);
}
__device__ __forceinline__ void ldx4(unsigned* r, uint32_t addr) {
    asm volatile("ldmatrix.sync.aligned.m8n8.x4.shared.b16 {%0,%1,%2,%3}, [%4];"
                 : "=r"(r[0]), "=r"(r[1]), "=r"(r[2]), "=r"(r[3]) : "r"(addr));
}
__device__ __forceinline__ void ldx2(unsigned* r, uint32_t addr) {
    asm volatile("ldmatrix.sync.aligned.m8n8.x2.shared.b16 {%0,%1}, [%2];"
                 : "=r"(r[0]), "=r"(r[1]) : "r"(addr));
}
__device__ __forceinline__ void mma16816(float* c, const unsigned* a, const unsigned* b) {
    asm volatile(
        "mma.sync.aligned.m16n8k16.row.col.f32.f16.f16.f32 "
        "{%0,%1,%2,%3}, {%4,%5,%6,%7}, {%8,%9}, {%0,%1,%2,%3};"
        : "+f"(c[0]), "+f"(c[1]), "+f"(c[2]), "+f"(c[3])
        : "r"(a[0]), "r"(a[1]), "r"(a[2]), "r"(a[3]), "r"(b[0]), "r"(b[1]));
}
__device__ __forceinline__ void cpasync16(uint32_t saddr, const void* gptr) {
    asm volatile("cp.async.cg.shared.global [%0], [%1], 16;"
                 :: "r"(saddr), "l"(gptr) : "memory");
}
#define CP_COMMIT() asm volatile("cp.async.commit_group;" ::: "memory")
#define CP_WAIT0()  asm volatile("cp.async.wait_group 0;" ::: "memory")

__device__ __forceinline__ uint32_t packsplit(float x0, float x1, uint32_t& lo) {
    __half h0 = __float2half_rn(x0), h1 = __float2half_rn(x1);
    float r0 = x0 - __half2float(h0);
    float r1 = x1 - __half2float(h1);
    __half l0 = __float2half_rn(r0), l1 = __float2half_rn(r1);
    lo = (uint32_t)__half_as_ushort(l0) | ((uint32_t)__half_as_ushort(l1) << 16);
    return (uint32_t)__half_as_ushort(h0) | ((uint32_t)__half_as_ushort(h1) << 16);
}
__device__ __forceinline__ uint32_t packq(float x0, float x1) {
    return (uint32_t)__half_as_ushort(__float2half_rn(x0)) |
           ((uint32_t)__half_as_ushort(__float2half_rn(x1)) << 16);
}

// ============ 2-term GEMM with transposing epilogue + exact el/er ============
// A: [M,K] fp32 exact hi/lo split; B: fp16 quantized [N][K].
// Producer accumulates exact el/er = A-row . wv (rank-1 logit trick).
// Epilogue writes transposed fp16 plane htQ [b][feat][node] + el/er.
// TR 1: gridDim.x == 2, only blockIdx.x == 0 writes el/er. TR 2: gridDim.x == 1.
template <int TR>
__global__ void __launch_bounds__(256, 2)
tc_gemm2t(const float* __restrict__ A, const __half* __restrict__ Bq, int K,
          const float* __restrict__ wv, int NF,
          __half* __restrict__ htQ,
          float* __restrict__ elO, float* __restrict__ erO)
{
    extern __shared__ char smem[];
    float* ws = (float*)smem;                  // [2*K] logit weights (<= 4 KB)
    constexpr int BASE = 4096;
    constexpr int BUF = 24576;                 // A_hi 8K | A_lo 8K | B 8K
    constexpr int OAH = 0, OAL = 8192, OBQ = 16384;

    const int m0 = blockIdx.y * 128;
    const int n0 = blockIdx.x * 128;
    const int tid  = threadIdx.x;
    const int warp = tid >> 5, lane = tid & 31;
    const int mw = (warp >> 2) * 64;
    const int nw = (warp & 3) * 32;
    const uint32_t sb = smem_u32(smem) + BASE;

    for (int i = tid; i < 2 * K; i += 256) ws[i] = wv[i];
    __syncthreads();

    const int ar = tid >> 1;
    const int ac = (tid & 1) * 16;
    float va[16];
    float sl = 0.f, sr = 0.f;

    auto produce_load = [&](int c) {
        const int k0 = c << 5;
        const float4* Sp = (const float4*)(A + (long long)(m0 + ar) * K + k0 + ac);
#pragma unroll
        for (int q = 0; q < 4; q++) {
            float4 f = Sp[q];
            va[q * 4 + 0] = f.x; va[q * 4 + 1] = f.y;
            va[q * 4 + 2] = f.z; va[q * 4 + 3] = f.w;
        }
        const float* wl = ws + k0 + ac;
        const float* wr = ws + K + k0 + ac;
#pragma unroll
        for (int e = 0; e < 16; e++) {
            sl = fmaf(va[e], wl[e], sl);
            sr = fmaf(va[e], wr[e], sr);
        }
    };
    auto produce_B = [&](int c, int buf) {
        const int k0 = c << 5;
        const uint32_t dB = sb + buf * BUF + OBQ;
#pragma unroll
        for (int rep = 0; rep < 2; rep++) {
            int idx = tid + rep * 256;
            int row = idx >> 2, q = idx & 3;
            uint32_t so = sw64(row * 64 + q * 16);
            cpasync16(dB + so, Bq + (long long)(n0 + row) * K + k0 + q * 8);
        }
        CP_COMMIT();
    };
    auto produce_store = [&](int buf) {
        char* base = smem + BASE + buf * BUF;
#pragma unroll
        for (int g = 0; g < 2; g++) {
            uint4 hq, lq;
            uint32_t* hw = (uint32_t*)&hq;
            uint32_t* lw = (uint32_t*)&lq;
#pragma unroll
            for (int e = 0; e < 4; e++)
                hw[e] = packsplit(va[g * 8 + e * 2], va[g * 8 + e * 2 + 1], lw[e]);
            uint32_t so = sw64(ar * 64 + ac * 2 + g * 16);
            *(uint4*)(base + OAH + so) = hq;
            *(uint4*)(base + OAL + so) = lq;
        }
    };

    float acc[4][4][4] = {};
    auto consume = [&](int buf) {
        const uint32_t aH = sb + buf * BUF + OAH;
        const uint32_t aL = sb + buf * BUF + OAL;
        const uint32_t bB = sb + buf * BUF + OBQ;
        const uint32_t aRow = (lane & 15);
        const uint32_t aKof = (lane >> 4) * 16;
        const uint32_t bRow = (lane & 7);
        const uint32_t bKof = ((lane >> 3) & 1) * 16;
#pragma unroll
        for (int ks = 0; ks < 2; ks++) {
            const uint32_t kb = ks * 32;
            unsigned ah[4][4], al[4][4], bh[4][2];
#pragma unroll
            for (int mt = 0; mt < 4; mt++) {
                uint32_t off = sw64((mw + mt * 16 + aRow) * 64 + kb + aKof);
                ldx4(ah[mt], aH + off);
                ldx4(al[mt], aL + off);
            }
#pragma unroll
            for (int nt = 0; nt < 4; nt++) {
                uint32_t off = sw64((nw + nt * 8 + bRow) * 64 + kb + bKof);
                ldx2(bh[nt], bB + off);
            }
#pragma unroll
            for (int mt = 0; mt < 4; mt++)
#pragma unroll
                for (int nt = 0; nt < 4; nt++)
                    mma16816(acc[mt][nt], ah[mt], bh[nt]);
#pragma unroll
            for (int mt = 0; mt < 4; mt++)
#pragma unroll
                for (int nt = 0; nt < 4; nt++)
                    mma16816(acc[mt][nt], al[mt], bh[nt]);
        }
    };

    const int nCh = K >> 5;
    produce_load(0);
    produce_B(0, 0);
    produce_store(0);
    CP_WAIT0();
    __syncthreads();
    int buf = 0;
    for (int c = 0; c < nCh; c++) {
        const bool more = (c + 1 < nCh);
        if (more) {
            produce_load(c + 1);
            produce_B(c + 1, buf ^ 1);
        }
        consume(buf);
        if (more) produce_store(buf ^ 1);
        CP_WAIT0();
        __syncthreads();
        buf ^= 1;
    }

    // ---- exact el/er write (rank-1 logits, fp32) ----
    sl += __shfl_xor_sync(0xFFFFFFFFu, sl, 1);
    sr += __shfl_xor_sync(0xFFFFFFFFu, sr, 1);
    if ((tid & 1) == 0 && (TR == 2 || blockIdx.x == 0)) {
        elO[m0 + (tid >> 1)] = sl;
        erO[m0 + (tid >> 1)] = sr;
    }

    // ---- transposing epilogue ----
    const int r0 = lane >> 2;
    const int cc = (lane & 3) * 2;
    __syncthreads();
    float* ts = (float*)smem;          // overlaps ws+buffers (both dead now)
#pragma unroll
    for (int mt = 0; mt < 4; mt++) {
#pragma unroll
        for (int nt = 0; nt < 4; nt++) {
            float* a4 = acc[mt][nt];
            const int row = mw + mt * 16 + r0;
            const int col = nw + nt * 8 + cc;
            ts[row * 129 + col]           = a4[0];
            ts[row * 129 + col + 1]       = a4[1];
            ts[(row + 8) * 129 + col]     = a4[2];
            ts[(row + 8) * 129 + col + 1] = a4[3];
        }
    }
    __syncthreads();
    {
        const int f  = tid >> 1;
        const int hf = tid & 1;
        const int b  = m0 >> 10;
        const int node0 = (m0 & 1023) + hf * 64;
        __half* dh = htQ + ((long long)(b * NF + n0 + f) * NN) + node0;
#pragma unroll
        for (int i0 = 0; i0 < 64; i0 += 8) {
            uint4 hq;
            uint32_t* hw = (uint32_t*)&hq;
#pragma unroll
            for (int e = 0; e < 4; e++) {
                float x0 = ts[(hf * 64 + i0 + e * 2)     * 129 + f];
                float x1 = ts[(hf * 64 + i0 + e * 2 + 1) * 129 + f];
                hw[e] = packq(x0, x1);
            }
            *(uint4*)(dh + i0) = hq;
        }
    }
}

// ============ pure fp16 GEMM (GEMM2/GEMM4), BK=64, SW128 ====================
template <int EPI>
__global__ void __launch_bounds__(256, 2)
tc_gemmq(const __half* __restrict__ Aq, const __half* __restrict__ Bq,
         float* __restrict__ C, int N, int K,
         long long sA, long long sB, long long sC)
{
    extern __shared__ char smem[];
    constexpr int BUF = 32768;
    constexpr int OA = 0, OB = 16384;

    const int bz = blockIdx.z;
    Aq += (long long)bz * sA;
    Bq += (long long)bz * sB;
    C  += (long long)bz * sC;

    const int m0 = blockIdx.y * 128;
    const int n0 = blockIdx.x * 128;
    const int tid  = threadIdx.x;
    const int warp = tid >> 5, lane = tid & 31;
    const int mw = (warp >> 2) * 64;
    const int nw = (warp & 3) * 32;
    const uint32_t sb = smem_u32(smem);

    auto produce = [&](int c, int buf) {
        const int k0 = c << 6;
        const uint32_t dA = sb + buf * BUF + OA;
        const uint32_t dB = sb + buf * BUF + OB;
#pragma unroll
        for (int rep = 0; rep < 4; rep++) {
            int idx = tid + rep * 256;
            int row = idx >> 3, q = idx & 7;
            uint32_t so = sw128(row * 128 + q * 16);
            cpasync16(dA + so, Aq + (long long)(m0 + row) * K + k0 + q * 8);
            cpasync16(dB + so, Bq + (long long)(n0 + row) * K + k0 + q * 8);
        }
        CP_COMMIT();
    };

    float acc[4][4][4] = {};
    auto consume = [&](int buf) {
        const uint32_t aB = sb + buf * BUF + OA;
        const uint32_t bB = sb + buf * BUF + OB;
        const uint32_t aRow = (lane & 15);
        const uint32_t aKof = (lane >> 4) * 16;
        const uint32_t bRow = (lane & 7);
        const uint32_t bKof = ((lane >> 3) & 1) * 16;
#pragma unroll
        for (int ks = 0; ks < 4; ks++) {
            const uint32_t kb = ks * 32;
            unsigned ah[4][4], bh[4][2];
#pragma unroll
            for (int mt = 0; mt < 4; mt++) {
                uint32_t off = sw128((mw + mt * 16 + aRow) * 128 + kb + aKof);
                ldx4(ah[mt], aB + off);
            }
#pragma unroll
            for (int nt = 0; nt < 4; nt++) {
                uint32_t off = sw128((nw + nt * 8 + bRow) * 128 + kb + bKof);
                ldx2(bh[nt], bB + off);
            }
#pragma unroll
            for (int mt = 0; mt < 4; mt++)
#pragma unroll
                for (int nt = 0; nt < 4; nt++)
                    mma16816(acc[mt][nt], ah[mt], bh[nt]);
        }
    };

    const int nCh = K >> 6;
    produce(0, 0);
    CP_WAIT0();
    __syncthreads();
    int buf = 0;
    for (int c = 0; c < nCh; c++) {
        if (c + 1 < nCh) produce(c + 1, buf ^ 1);
        consume(buf);
        CP_WAIT0();
        __syncthreads();
        buf ^= 1;
    }

    const int r0 = lane >> 2;
    const int cc = (lane & 3) * 2;
#pragma unroll
    for (int mt = 0; mt < 4; mt++) {
#pragma unroll
        for (int nt = 0; nt < 4; nt++) {
            float* a4 = acc[mt][nt];
            if (EPI == 1) {
#pragma unroll
                for (int e = 0; e < 4; e++)
                    a4[e] = a4[e] > 0.f ? a4[e] : (__expf(a4[e]) - 1.f);
            }
            const int col = n0 + nw + nt * 8 + cc;
            const int row = m0 + mw + mt * 16 + r0;
            *(float2*)&C[(long long)row * N + col]       = make_float2(a4[0], a4[1]);
            *(float2*)&C[(long long)(row + 8) * N + col] = make_float2(a4[2], a4[3]);
        }
    }
}

// ============ attention generator ===========================================
template <int WRITE32>
__global__ void __launch_bounds__(256)
att_gen(const float* __restrict__ el, const float* __restrict__ er,
        __half* __restrict__ attq, float* __restrict__ att32)
{
    __shared__ float ser[NN];
    __shared__ float red[4][8];
    __shared__ float sstat[2];
    const int bz = blockIdx.y;
    const int tid = threadIdx.x;
    const int warp = tid >> 5, lane = tid & 31;

    float mnl = 1e30f, mxl = -1e30f, mnr = 1e30f, mxr = -1e30f;
    for (int i = tid; i < NN; i += 256) {
        float l = el[bz * NN + i];
        float r = er[bz * NN + i];
        ser[i] = r;
        mnl = fminf(mnl, l); mxl = fmaxf(mxl, l);
        mnr = fminf(mnr, r); mxr = fmaxf(mxr, r);
    }
#pragma unroll
    for (int o = 16; o; o >>= 1) {
        mnl = fminf(mnl, __shfl_xor_sync(0xFFFFFFFFu, mnl, o));
        mxl = fmaxf(mxl, __shfl_xor_sync(0xFFFFFFFFu, mxl, o));
        mnr = fminf(mnr, __shfl_xor_sync(0xFFFFFFFFu, mnr, o));
        mxr = fmaxf(mxr, __shfl_xor_sync(0xFFFFFFFFu, mxr, o));
    }
    if (lane == 0) { red[0][warp] = mnl; red[1][warp] = mxl; red[2][warp] = mnr; red[3][warp] = mxr; }
    __syncthreads();
    if (tid == 0) {
        float a0 = red[0][0], a1 = red[1][0], a2 = red[2][0], a3 = red[3][0];
#pragma unroll
        for (int i = 1; i < 8; i++) {
            a0 = fminf(a0, red[0][i]); a1 = fmaxf(a1, red[1][i]);
            a2 = fminf(a2, red[2][i]); a3 = fmaxf(a3, red[3][i]);
        }
        float lo = a0 + a2, hi = a1 + a3;
        float mn = lo >= 0.f ? lo : 0.01f * lo;
        float mx = hi >= 0.f ? hi : 0.01f * hi;
        sstat[0] = mn;
        sstat[1] = 30.f / (mx - mn);
    }
    __syncthreads();
    const float mn = sstat[0], kk = sstat[1];

    const int row = blockIdx.x * 8 + warp;
    const float elv = el[bz * NN + row];
    __half* aq = attq + ((long long)bz * NN + row) * NN;
    float* a32 = WRITE32 ? (att32 + ((long long)bz * NN + row) * NN) : nullptr;

    for (int j0 = lane * 4; j0 < NN; j0 += 128) {
        float4 r4 = *(const float4*)&ser[j0];
        float s0, s1, s2, s3;
        {
            float x = elv + r4.x; float lr = x >= 0.f ? x : 0.01f * x;
            s0 = fast_sigmoid_z(fmaf(lr - mn, kk, -20.f));
        }
        {
            float x = elv + r4.y; float lr = x >= 0.f ? x : 0.01f * x;
            s1 = fast_sigmoid_z(fmaf(lr - mn, kk, -20.f));
        }
        {
            float x = elv + r4.z; float lr = x >= 0.f ? x : 0.01f * x;
            s2 = fast_sigmoid_z(fmaf(lr - mn, kk, -20.f));
        }
        {
            float x = elv + r4.w; float lr = x >= 0.f ? x : 0.01f * x;
            s3 = fast_sigmoid_z(fmaf(lr - mn, kk, -20.f));
        }
        uint2 hv;
        hv.x = packq(s0, s1);
        hv.y = packq(s2, s3);
        *(uint2*)(aq + j0) = hv;
        if (WRITE32) *(float4*)(a32 + j0) = make_float4(s0, s1, s2, s3);
    }
}

// ---------------- transpose + fp16 quantize (weights) -----------------------
__global__ void prepT(const float* __restrict__ src, __half* __restrict__ dq,
                      int R, int Cc)
{
    __shared__ float t[32][33];
    const int c0 = blockIdx.x * 32;
    const int r0 = blockIdx.y * 32;
    const int tx = threadIdx.x, ty = threadIdx.y;
#pragma unroll
    for (int i = ty; i < 32; i += 8)
        t[i][tx] = src[(long long)(r0 + i) * Cc + c0 + tx];
    __syncthreads();
#pragma unroll
    for (int i = ty; i < 32; i += 8)
        dq[(long long)(c0 + i) * R + r0 + tx] = __float2half_rn(t[tx][i]);
}

// ---------------- wv = W @ [aL | aR] (exact fp32 logit weights) -------------
__global__ void wdot(const float* __restrict__ W, const float* __restrict__ a,
                     float* __restrict__ wv, int Rk, int Fo)
{
    const int row  = blockIdx.x * 8 + (threadIdx.x >> 5);
    const int lane = threadIdx.x & 31;
    const float* wr = W + (long long)row * Fo;
    float sl = 0.f, sr = 0.f;
    for (int c = lane; c < Fo; c += 32) {
        float v = wr[c];
        sl = fmaf(v, a[c], sl);
        sr = fmaf(v, a[Fo + c], sr);
    }
#pragma unroll
    for (int o = 16; o; o >>= 1) {
        sl += __shfl_xor_sync(0xFFFFFFFFu, sl, o);
        sr += __shfl_xor_sync(0xFFFFFFFFu, sr, o);
    }
    if (lane == 0) { wv[row] = sl; wv[Rk + row] = sr; }
}

// ---------------- gv = g2 @ Wg ----------------------------------------------
__global__ void gv_kernel(const float* __restrict__ g2, const float* __restrict__ Wg,
                          float* __restrict__ gv)
{
    const int row  = (blockIdx.x * blockDim.x + threadIdx.x) >> 5;
    const int lane = threadIdx.x & 31;
    const float* gp = g2 + (long long)row * H2_;
    float s = fmaf(gp[lane], Wg[lane], gp[lane + 32] * Wg[lane + 32]);
    s = fmaf(gp[lane + 64], Wg[lane + 64], s);
    s = fmaf(gp[lane + 96], Wg[lane + 96], s);
#pragma unroll
    for (int o = 16; o; o >>= 1) s += __shfl_xor_sync(0xFFFFFFFFu, s, o);
    if (lane == 0) gv[row] = s;
}

// ---------------- out = leaky(att2q @ gv + bg), fp16 matrix ------------------
__global__ void z_kernel(const __half* __restrict__ fc2h, const float* __restrict__ gv,
                         const float* __restrict__ bg, float* __restrict__ out)
{
    const int row  = (blockIdx.x * blockDim.x + threadIdx.x) >> 5;
    const int lane = threadIdx.x & 31;
    const int b = row >> 10;
    const __half* fr = fc2h + (long long)row * NN;
    const float* gr = gv + b * NN;
    float s = 0.f;
#pragma unroll
    for (int j = lane * 4; j < NN; j += 128) {
        uint2 hv = *(const uint2*)(fr + j);
        __half2 f01 = *(__half2*)&hv.x;
        __half2 f23 = *(__half2*)&hv.y;
        float4 g = *(const float4*)&gr[j];
        s = fmaf(__low2float(f01),  g.x, s);
        s = fmaf(__high2float(f01), g.y, s);
        s = fmaf(__low2float(f23),  g.z, s);
        s = fmaf(__high2float(f23), g.w, s);
    }
#pragma unroll
    for (int o = 16; o; o >>= 1) s += __shfl_xor_sync(0xFFFFFFFFu, s, o);
    if (lane == 0) {
        float z = s + bg[0];
        out[row] = z >= 0.f ? z : 0.01f * z;
    }
}

// ---------------------------------------------------------------------------
template <typename T>
static T* sym_p(const void* s)
{
    void* p = nullptr;
    cudaGetSymbolAddress(&p, s);
    return (T*)p;
}

extern "C" void kernel_launch(void* const* d_in, const int* in_sizes, int n_in,
                              void* d_out, int out_size)
{
    const float* x  = (const float*)d_in[0];
    const float* W1 = (const float*)d_in[2];
    const float* a1 = (const float*)d_in[3];
    const float* W2 = (const float*)d_in[4];
    const float* a2 = (const float*)d_in[5];
    const float* Wg = (const float*)d_in[6];
    const float* bg = (const float*)d_in[7];

    float* out = (float*)d_out;
    float* fc2 = out + (long long)B_ * NN;
    float* g2  = fc2 + (long long)B_ * NN * NN;

    float* g1   = sym_p<float>(d_g1);
    float* el   = sym_p<float>(d_el);
    float* er   = sym_p<float>(d_er);
    float* gv   = sym_p<float>(d_gv);
    float* w1a  = sym_p<float>(d_w1a);
    float* w2a  = sym_p<float>(d_w2a);
    __half* att1q = sym_p<__half>(d_att1q);
    __half* att2q = sym_p<__half>(d_att2q);
    __half* ht1  = sym_p<__half>(d_ht1);
    __half* ht2  = sym_p<__half>(d_ht2);
    __half* wt1q = sym_p<__half>(d_wt1q);
    __half* wt2q = sym_p<__half>(d_wt2q);

    const int SMBQ   = 2 * 32768;           // 64 KB (pure fp16 GEMM, BK=64)
    const int SMB_TR = 128 * 129 * 4 + 512; // 66.5 KB (staging dominates)
    cudaFuncSetAttribute(tc_gemm2t<1>, cudaFuncAttributeMaxDynamicSharedMemorySize, SMB_TR);
    cudaFuncSetAttribute(tc_gemm2t<2>, cudaFuncAttributeMaxDynamicSharedMemorySize, SMB_TR);
    cudaFuncSetAttribute(tc_gemmq<1>, cudaFuncAttributeMaxDynamicSharedMemorySize, SMBQ);
    cudaFuncSetAttribute(tc_gemmq<0>, cudaFuncAttributeMaxDynamicSharedMemorySize, SMBQ);

    const int rowsTot = B_ * NN;              // 32768
    const dim3 tp(32, 8);

    // ===== preps: quantized transposed weights + exact rank-1 logit vectors ==
    prepT<<<dim3(H1_ / 32, FIN / 32, 1), tp>>>(W1, wt1q, FIN, H1_);
    prepT<<<dim3(H2_ / 32, H1_ / 32, 1), tp>>>(W2, wt2q, H1_, H2_);
    wdot<<<FIN / 8, 256>>>(W1, a1, w1a, FIN, H1_);
    wdot<<<H1_ / 8, 256>>>(W2, a2, w2a, H1_, H2_);

    // ===== Layer 1 =====
    // h1 = x @ W1 (2-term; el/er exact via rank-1); writes ht1 + el/er
    tc_gemm2t<1><<<dim3(H1_ / 128, rowsTot / 128, 1), 256, SMB_TR>>>(
        x, wt1q, FIN, w1a, H1_, ht1, el, er);
    att_gen<0><<<dim3(NN / 8, B_), 256>>>(el, er, att1q, nullptr);
    // g1 = elu(att1 @ h1)
    tc_gemmq<1><<<dim3(H1_ / 128, NN / 128, B_), 256, SMBQ>>>(
        att1q, ht1, g1, H1_, NN,
        (long long)NN * NN, (long long)H1_ * NN, (long long)NN * H1_);

    // ===== Layer 2 =====
    // h2 = g1 @ W2 (2-term; el/er exact via rank-1); writes ht2 + el/er
    tc_gemm2t<2><<<dim3(H2_ / 128, rowsTot / 128, 1), 256, SMB_TR>>>(
        g1, wt2q, H1_, w2a, H2_, ht2, el, er);
    // att2: fp16 operand + fp32 fc2 output
    att_gen<1><<<dim3(NN / 8, B_), 256>>>(el, er, att2q, fc2);
    // g2 = att2 @ h2
    tc_gemmq<0><<<dim3(H2_ / 128, NN / 128, B_), 256, SMBQ>>>(
        att2q, ht2, g2, H2_, NN,
        (long long)NN * NN, (long long)H2_ * NN, (long long)NN * H2_);

    // ===== Head: out = leaky(fc2 @ (g2 @ Wg) + bg), fc2 via fp16 att2q =====
    gv_kernel<<<rowsTot / 8, 256>>>(g2, Wg, gv);
    z_kernel<<<rowsTot / 8, 256>>>(att2q, gv, bg, out);
}